// round 13
// baseline (speedup 1.0000x reference)
#include <cuda_runtime.h>
#include <cuda_fp16.h>

// ---------------------------------------------------------------------------
// EMA Vector Quantizer, round 13:
//   stage 1: 1-pass fp16 HMMA argmin + scatter; BM=64, 2 CTAs/SM, m32 x n32;
//            branchless epilogue with 8-bit index embedded in score mantissa
//            (pure FMNMX chains, no FSETP/FSEL)
//   stage 2: 3-pass split-fp16 re-scan of ambiguous rows
//   stage 3: parallel exact fp32 scan + apply
// ---------------------------------------------------------------------------

#define NUM_E   4096
#define CDIM    64
#define NVEC    65536
#define BM      64
#define BN      128
#define NTILES  (NUM_E / BN)   // 32
#define THREADS 256
#define MARGIN1 0.09f
#define MARGIN2 1.0e-3f
#define FPARTS  8

#define OFF_Q    0
#define OFF_LOSS 4194304
#define OFF_IDX  4194305
#define OFF_W    (OFF_IDX + NVEC)
#define OFF_CS   (OFF_W + NUM_E * CDIM)
#define OFF_EW   (OFF_CS + NUM_E)

// stage-1 smem: X 8K + 2 x (W 16K + wn 512B)
#define SM_XH      0
#define SM_WBUF(b) (8192 + (b) * 16896)
#define SM_WN(b)   (SM_WBUF(b) + 16384)
#define SMEM_TOTAL (8192 + 2 * 16896)       // 41984

// stage-2 smem: 2 x (Whi 16K | Wlo 16K | wn .5K)
#define A_XH     0
#define A_XL     4096
#define A_VID    8192
#define A_COLD   8320
#define A_CNEW   8448
#define A_WB(b)  (9216 + (b) * 33280)
#define A_WLO(b) (A_WB(b) + 16384)
#define A_WN(b)  (A_WB(b) + 32768)
#define A_SMEM   (9216 + 2 * 33280)         // 75776

// device scratch
__device__ __half g_wth[CDIM * NUM_E];
__device__ __half g_wtl[CDIM * NUM_E];
__device__ float  g_wn[NUM_E];
__device__ float  g_counts[NUM_E];
__device__ float  g_dw[NUM_E * CDIM];
__device__ int    g_bestk[NVEC];
__device__ int    g_amb[NVEC];
__device__ int    g_namb;
__device__ int    g_amb2[NVEC];
__device__ int    g_namb2;
__device__ unsigned long long g_fixbest[NVEC];
__device__ float  g_loss;
__device__ float  g_n;

// ---- PTX helpers -----------------------------------------------------------
__device__ __forceinline__ unsigned smem_u32(const void* p) {
    return (unsigned)__cvta_generic_to_shared(p);
}
__device__ __forceinline__ void ldsm4(unsigned* r, unsigned addr) {
    asm volatile("ldmatrix.sync.aligned.m8n8.x4.shared.b16 {%0,%1,%2,%3}, [%4];"
                 : "=r"(r[0]), "=r"(r[1]), "=r"(r[2]), "=r"(r[3]) : "r"(addr));
}
__device__ __forceinline__ void ldsm4t(unsigned* r, unsigned addr) {
    asm volatile("ldmatrix.sync.aligned.m8n8.x4.trans.shared.b16 {%0,%1,%2,%3}, [%4];"
                 : "=r"(r[0]), "=r"(r[1]), "=r"(r[2]), "=r"(r[3]) : "r"(addr));
}
__device__ __forceinline__ void mma16816(float* c, const unsigned* a,
                                         unsigned b0, unsigned b1) {
    asm volatile("mma.sync.aligned.m16n8k16.row.col.f32.f16.f16.f32 "
                 "{%0,%1,%2,%3}, {%4,%5,%6,%7}, {%8,%9}, {%0,%1,%2,%3};"
                 : "+f"(c[0]), "+f"(c[1]), "+f"(c[2]), "+f"(c[3])
                 : "r"(a[0]), "r"(a[1]), "r"(a[2]), "r"(a[3]), "r"(b0), "r"(b1));
}
__device__ __forceinline__ void cpa16(unsigned dst, const void* src) {
    asm volatile("cp.async.cg.shared.global [%0], [%1], 16;"
                 :: "r"(dst), "l"(src) : "memory");
}
__device__ __forceinline__ unsigned encf(float f) {
    unsigned u = __float_as_uint(f);
    return (u & 0x80000000u) ? ~u : (u | 0x80000000u);
}
// embed 8-bit tag into low mantissa bits
__device__ __forceinline__ float embed8(float s, int tag) {
    return __uint_as_float((__float_as_uint(s) & ~255u) | (unsigned)tag);
}

// ---------------------------------------------------------------------------
// prep kernels (split: keeps argmin as 4th launch for ncu)
// ---------------------------------------------------------------------------
__global__ void prep_zero_kernel() {
    int i = blockIdx.x * blockDim.x + threadIdx.x;   // 65536
    float4 z = make_float4(0.f, 0.f, 0.f, 0.f);
    reinterpret_cast<float4*>(g_dw)[i] = z;
    if (i < NUM_E) g_counts[i] = 0.0f;
    if (i == 0) { g_loss = 0.0f; g_n = 0.0f; g_namb = 0; g_namb2 = 0; }
}

__global__ void prep_wn_kernel(const float* __restrict__ weight) {
    int k = blockIdx.x * blockDim.x + threadIdx.x;   // 4096
    const float4* wr = reinterpret_cast<const float4*>(weight + (size_t)k * CDIM);
    float s = 0.0f;
#pragma unroll
    for (int j = 0; j < CDIM / 4; ++j) {
        float4 v = wr[j];
        s += v.x * v.x + v.y * v.y + v.z * v.z + v.w * v.w;
    }
    g_wn[k] = s;
}

__global__ void prep_cvt_kernel(const float* __restrict__ weight) {
    __shared__ float tile[64][65];
    const int tid = threadIdx.x;
    const int code0 = blockIdx.x * 64;
#pragma unroll
    for (int it = 0; it < 4; ++it) {
        int flat = it * 256 + tid;
        int code = flat >> 4, j = flat & 15;
        float4 v = reinterpret_cast<const float4*>(weight)[(size_t)(code0 + code) * 16 + j];
        tile[code][j * 4 + 0] = v.x;
        tile[code][j * 4 + 1] = v.y;
        tile[code][j * 4 + 2] = v.z;
        tile[code][j * 4 + 3] = v.w;
    }
    __syncthreads();
#pragma unroll
    for (int it = 0; it < 16; ++it) {
        int flat = it * 256 + tid;
        int c = flat >> 6, code = flat & 63;
        float w = tile[code][c];
        __half hi = __float2half_rn(w);
        __half lo = __float2half_rn(w - __half2float(hi));
        g_wth[(size_t)c * NUM_E + code0 + code] = hi;
        g_wtl[(size_t)c * NUM_E + code0 + code] = lo;
    }
}

// ---------------------------------------------------------------------------
// stage 1 (fused): argmin + scatter; BM=64, 2 CTAs/SM, m32 x n32,
// branchless index-embedded epilogue
// ---------------------------------------------------------------------------
__global__ void __launch_bounds__(THREADS, 2)
argmin_kernel(const float* __restrict__ inputs,
              const float* __restrict__ weight,
              float* __restrict__ out)
{
    extern __shared__ char smem[];
    const unsigned sb = smem_u32(smem);
    const int tid  = threadIdx.x;
    const int lane = tid & 31;
    const int wid  = tid >> 5;
    const int wm   = wid >> 2;     // 0..1 (m32 slice)
    const int wnh  = wid & 3;      // 0..3 (n32 group)

    const int n0  = blockIdx.x * BM;
    const int bB  = n0 >> 12;
    const int hw0 = n0 & 4095;

    // ---- load X (64 rows x 64 dims), fp16, swizzled ----------------------
    const float* xb = inputs + (size_t)bB * (CDIM * 4096) + hw0;
#pragma unroll
    for (int it = 0; it < 2; ++it) {
        int idx = it * 256 + tid;
        int c = (idx & 31) * 2;
        int r = (idx >> 5) * 4;
        float4 f0 = *reinterpret_cast<const float4*>(xb + (size_t)c * 4096 + r);
        float4 f1 = *reinterpret_cast<const float4*>(xb + (size_t)(c + 1) * 4096 + r);
        const float* p0 = &f0.x; const float* p1 = &f1.x;
#pragma unroll
        for (int q = 0; q < 4; ++q) {
            int row = r + q;
            unsigned off = row * 128 + (((c >> 3) ^ (row & 7)) * 16) + (c & 7) * 2;
            *reinterpret_cast<__half2*>(smem + SM_XH + off) =
                __floats2half2_rn(p0[q], p1[q]);
        }
    }
    __syncthreads();

    // A fragments: m32 x k64
    unsigned afh[2][4][4];
#pragma unroll
    for (int i = 0; i < 2; ++i)
#pragma unroll
        for (int k = 0; k < 4; ++k) {
            int row = wm * 32 + i * 16 + (lane & 15);
            int ch  = (k * 2 + (lane >> 4)) ^ (row & 7);
            ldsm4(afh[i][k], sb + SM_XH + row * 128 + ch * 16);
        }

    unsigned boff[4][2];
#pragma unroll
    for (int k = 0; k < 4; ++k)
#pragma unroll
        for (int jj = 0; jj < 2; ++jj) {
            int row = k * 16 + (lane & 15);
            int ch  = (wnh * 4 + jj * 2 + (lane >> 4)) ^ (row & 7);
            boff[k][jj] = row * 256 + ch * 16;
        }

    float best[4], best2[4];
#pragma unroll
    for (int s = 0; s < 4; ++s) { best[s] = 3.4e38f; best2[s] = 3.4e38f; }

    const int wnidx = (wnh * 32 + 2 * (lane & 3)) * 4;

    // prologue: tile 0 into buf 0
    {
#pragma unroll
        for (int j = 0; j < 4; ++j) {
            int idx = j * 256 + tid;
            int row = idx >> 4, c = idx & 15;
            cpa16(sb + SM_WBUF(0) + row * 256 + ((c ^ (row & 7)) * 16),
                  g_wth + (size_t)row * NUM_E + c * 8);
        }
        if (tid < 32) cpa16(sb + SM_WN(0) + tid * 16, g_wn + tid * 4);
        asm volatile("cp.async.commit_group;" ::: "memory");
    }

    for (int t = 0; t < NTILES; ++t) {
        if (t + 1 < NTILES) {
            int kt = (t + 1) * BN, b = (t + 1) & 1;
#pragma unroll
            for (int j = 0; j < 4; ++j) {
                int idx = j * 256 + tid;
                int row = idx >> 4, c = idx & 15;
                cpa16(sb + SM_WBUF(b) + row * 256 + ((c ^ (row & 7)) * 16),
                      g_wth + (size_t)row * NUM_E + kt + c * 8);
            }
            if (tid < 32) cpa16(sb + SM_WN(b) + tid * 16, g_wn + kt + tid * 4);
            asm volatile("cp.async.commit_group;" ::: "memory");
            asm volatile("cp.async.wait_group 1;" ::: "memory");
        } else {
            asm volatile("cp.async.wait_group 0;" ::: "memory");
        }
        __syncthreads();

        const unsigned whib = sb + SM_WBUF(t & 1);
        float acc[2][4][4];
#pragma unroll
        for (int i = 0; i < 2; ++i)
#pragma unroll
            for (int j = 0; j < 4; ++j)
#pragma unroll
                for (int e = 0; e < 4; ++e) acc[i][j][e] = 0.0f;

#pragma unroll
        for (int k = 0; k < 4; ++k) {
            unsigned bh[2][4];
#pragma unroll
            for (int jj = 0; jj < 2; ++jj) ldsm4t(bh[jj], whib + boff[k][jj]);
#pragma unroll
            for (int i = 0; i < 2; ++i)
#pragma unroll
                for (int j = 0; j < 4; ++j)
                    mma16816(acc[i][j], afh[i][k], bh[j >> 1][(j & 1) * 2],
                             bh[j >> 1][(j & 1) * 2 + 1]);
        }

        // ---- branchless epilogue: embed (t,j,e) tag, pure FMNMX ----------
        const int tagt = t << 3;
        const char* wnst = smem + SM_WN(t & 1);
#pragma unroll
        for (int j = 0; j < 4; ++j) {
            float2 wn2 = *reinterpret_cast<const float2*>(wnst + wnidx + j * 32);
            int tag0 = tagt + j * 2;
#pragma unroll
            for (int i = 0; i < 2; ++i) {
#pragma unroll
                for (int hlf = 0; hlf < 2; ++hlf) {
                    int sl = i * 2 + hlf;
                    float s0 = embed8(fmaf(-2.0f, acc[i][j][hlf * 2 + 0], wn2.x), tag0);
                    float s1 = embed8(fmaf(-2.0f, acc[i][j][hlf * 2 + 1], wn2.y), tag0 + 1);
                    best2[sl] = fminf(best2[sl], fmaxf(best[sl], s0));
                    best[sl]  = fminf(best[sl], s0);
                    best2[sl] = fminf(best2[sl], fmaxf(best[sl], s1));
                    best[sl]  = fminf(best[sl], s1);
                }
            }
        }
        __syncthreads();
    }

    // decode embedded tags -> code indices (per thread, before reductions)
    int bk[4];
#pragma unroll
    for (int s = 0; s < 4; ++s) {
        int loc = (int)(__float_as_uint(best[s]) & 255u);
        bk[s] = (loc >> 3) * BN + wnh * 32 + 2 * (lane & 3) + ((loc >> 1) & 3) * 8 + (loc & 1);
    }

    // quad reduction (rows constant across lane&3)
#pragma unroll
    for (int off = 1; off <= 2; off <<= 1) {
#pragma unroll
        for (int s = 0; s < 4; ++s) {
            float ob  = __shfl_xor_sync(0xffffffffu, best[s], off);
            float ob2 = __shfl_xor_sync(0xffffffffu, best2[s], off);
            int   ok  = __shfl_xor_sync(0xffffffffu, bk[s], off);
            float nb2 = fminf(fminf(best2[s], ob2), fmaxf(best[s], ob));
            bool take = (ob < best[s]) || (ob == best[s] && ok < bk[s]);
            best[s] = take ? ob : best[s];
            bk[s]   = take ? ok : bk[s];
            best2[s] = nb2;
        }
    }

    // stage per (row, n-group), merge 4 groups (reuse X region)
    float* mB  = reinterpret_cast<float*>(smem);          // [4][64]
    float* mB2 = mB + 256;
    int*   mK  = reinterpret_cast<int*>(mB2 + 256);
    int*   idx_s = mK + 256;                               // [64]
    float* red   = reinterpret_cast<float*>(idx_s + 64);   // [8]
    __syncthreads();
    if ((lane & 3) == 0) {
#pragma unroll
        for (int s = 0; s < 4; ++s) {
            int row = wm * 32 + (s >> 1) * 16 + (lane >> 2) + (s & 1) * 8;
            mB [wnh * 64 + row] = best[s];
            mB2[wnh * 64 + row] = best2[s];
            mK [wnh * 64 + row] = bk[s];
        }
    }
    __syncthreads();
    if (tid < 64) {
        float nb = 3.4e38f; int nk = 0, ng = 0;
#pragma unroll
        for (int g = 0; g < 4; ++g) {
            float b = mB[g * 64 + tid];
            int   k = mK[g * 64 + tid];
            if (b < nb || (b == nb && k < nk)) { nb = b; nk = k; ng = g; }
        }
        float nb2 = 3.4e38f;
#pragma unroll
        for (int g = 0; g < 4; ++g) {
            float cand = (g == ng) ? mB2[g * 64 + tid]
                                   : fminf(mB[g * 64 + tid], mB2[g * 64 + tid]);
            nb2 = fminf(nb2, cand);
        }
        g_bestk[n0 + tid] = nk;
        idx_s[tid] = nk;
        out[OFF_IDX + n0 + tid] = (float)nk;
        atomicAdd(&g_counts[nk], 1.0f);
        bool amb = (nb2 - nb) < MARGIN1;
        unsigned m = __ballot_sync(0xffffffffu, amb);
        int basep = 0;
        if (lane == 0 && m) basep = atomicAdd(&g_namb, __popc(m));
        basep = __shfl_sync(0xffffffffu, basep, 0);
        if (amb) g_amb[basep + __popc(m & ((1u << lane) - 1u))] = n0 + tid;
    }
    __syncthreads();

    // fused scatter: q, loss, dw for this block's 64 rows
    float* outq = out + OFF_Q + (size_t)bB * (CDIM * 4096) + hw0;
    float lsum = 0.0f;
#pragma unroll
    for (int it = 0; it < 4; ++it) {
        int u  = it * 256 + tid;
        int c  = u >> 4;
        int r4 = (u & 15) * 4;
        float4 x4 = *reinterpret_cast<const float4*>(xb + (size_t)c * 4096 + r4);
        int k0i = idx_s[r4 + 0], k1i = idx_s[r4 + 1];
        int k2i = idx_s[r4 + 2], k3i = idx_s[r4 + 3];
        float q0 = __ldg(weight + (size_t)k0i * CDIM + c);
        float q1 = __ldg(weight + (size_t)k1i * CDIM + c);
        float q2 = __ldg(weight + (size_t)k2i * CDIM + c);
        float q3 = __ldg(weight + (size_t)k3i * CDIM + c);
        *reinterpret_cast<float4*>(outq + (size_t)c * 4096 + r4) =
            make_float4(q0, q1, q2, q3);
        float d0 = x4.x - q0, d1 = x4.y - q1, d2 = x4.z - q2, d3 = x4.w - q3;
        lsum += d0 * d0 + d1 * d1 + d2 * d2 + d3 * d3;
        atomicAdd(&g_dw[k0i * CDIM + c], x4.x);
        atomicAdd(&g_dw[k1i * CDIM + c], x4.y);
        atomicAdd(&g_dw[k2i * CDIM + c], x4.z);
        atomicAdd(&g_dw[k3i * CDIM + c], x4.w);
    }
#pragma unroll
    for (int o = 16; o > 0; o >>= 1)
        lsum += __shfl_xor_sync(0xffffffffu, lsum, o);
    if (lane == 0) red[wid] = lsum;
    __syncthreads();
    if (tid == 0) {
        float s = 0.0f;
#pragma unroll
        for (int w = 0; w < 8; ++w) s += red[w];
        atomicAdd(&g_loss, s);
    }
}

// ---------------------------------------------------------------------------
// stage 2: 3-pass split-fp16 re-scan of ambiguous rows + in-place corrections
// ---------------------------------------------------------------------------
__global__ void __launch_bounds__(256, 1)
amb_kernel(const float* __restrict__ inputs,
           const float* __restrict__ weight,
           float* __restrict__ out)
{
    extern __shared__ char smem[];
    const unsigned sb = smem_u32(smem);
    const int tid  = threadIdx.x;
    const int lane = tid & 31;
    const int wid  = tid >> 5;
    const int wm   = wid >> 2;
    const int wnh  = wid & 3;

    const int namb = g_namb;
    if (namb == 0) return;

    int* avid = reinterpret_cast<int*>(smem + A_VID);
    int* cOld = reinterpret_cast<int*>(smem + A_COLD);
    int* cNew = reinterpret_cast<int*>(smem + A_CNEW);

    unsigned boff[4][2];
#pragma unroll
    for (int k = 0; k < 4; ++k)
#pragma unroll
        for (int jj = 0; jj < 2; ++jj) {
            int row = k * 16 + (lane & 15);
            int ch  = (wnh * 4 + jj * 2 + (lane >> 4)) ^ (row & 7);
            boff[k][jj] = row * 256 + ch * 16;
        }
    const int wnidx = (wnh * 32 + 2 * (lane & 3)) * 4;

    for (int base = blockIdx.x * 32; base < namb; base += gridDim.x * 32) {
        __syncthreads();

        if (tid < 32) {
            int li = base + tid;
            avid[tid] = g_amb[li < namb ? li : (namb - 1)];
        }
        __syncthreads();

        {
            int r = tid >> 3;
            int c0 = (tid & 7) * 8;
            int vid = avid[r];
            const float* xr = inputs + (size_t)(vid >> 12) * (CDIM * 4096) + (vid & 4095);
#pragma unroll
            for (int q = 0; q < 8; ++q) {
                int c = c0 + q;
                float v = xr[(size_t)c * 4096];
                __half hi = __float2half_rn(v);
                __half lo = __float2half_rn(v - __half2float(hi));
                unsigned off = r * 128 + (((c >> 3) ^ (r & 7)) * 16) + (c & 7) * 2;
                *reinterpret_cast<__half*>(smem + A_XH + off) = hi;
                *reinterpret_cast<__half*>(smem + A_XL + off) = lo;
            }
        }
        __syncthreads();

        unsigned afh[4][4], afl[4][4];
#pragma unroll
        for (int k = 0; k < 4; ++k) {
            int row = wm * 16 + (lane & 15);
            int ch  = (k * 2 + (lane >> 4)) ^ (row & 7);
            ldsm4(afh[k], sb + A_XH + row * 128 + ch * 16);
            ldsm4(afl[k], sb + A_XL + row * 128 + ch * 16);
        }

        float best[2], best2[2]; int bk[2];
#pragma unroll
        for (int s = 0; s < 2; ++s) { best[s] = 3.4e38f; best2[s] = 3.4e38f; bk[s] = 0; }

        {
#pragma unroll
            for (int j = 0; j < 4; ++j) {
                int idx = j * 256 + tid;
                int row = idx >> 4, c = idx & 15;
                unsigned dsw = row * 256 + ((c ^ (row & 7)) * 16);
                cpa16(sb + A_WB(0)  + dsw, g_wth + (size_t)row * NUM_E + c * 8);
                cpa16(sb + A_WLO(0) + dsw, g_wtl + (size_t)row * NUM_E + c * 8);
            }
            if (tid < 32) cpa16(sb + A_WN(0) + tid * 16, g_wn + tid * 4);
            asm volatile("cp.async.commit_group;" ::: "memory");
        }

        for (int t = 0; t < NTILES; ++t) {
            if (t + 1 < NTILES) {
                int kt = (t + 1) * BN, b = (t + 1) & 1;
#pragma unroll
                for (int j = 0; j < 4; ++j) {
                    int idx = j * 256 + tid;
                    int row = idx >> 4, c = idx & 15;
                    unsigned dsw = row * 256 + ((c ^ (row & 7)) * 16);
                    cpa16(sb + A_WB(b)  + dsw, g_wth + (size_t)row * NUM_E + kt + c * 8);
                    cpa16(sb + A_WLO(b) + dsw, g_wtl + (size_t)row * NUM_E + kt + c * 8);
                }
                if (tid < 32) cpa16(sb + A_WN(b) + tid * 16, g_wn + kt + tid * 4);
                asm volatile("cp.async.commit_group;" ::: "memory");
                asm volatile("cp.async.wait_group 1;" ::: "memory");
            } else {
                asm volatile("cp.async.wait_group 0;" ::: "memory");
            }
            __syncthreads();

            const unsigned whib = sb + A_WB(t & 1);
            const unsigned wlob = sb + A_WLO(t & 1);
            float acc[4][4];
#pragma unroll
            for (int j = 0; j < 4; ++j)
#pragma unroll
                for (int e = 0; e < 4; ++e) acc[j][e] = 0.0f;

#pragma unroll
            for (int k = 0; k < 4; ++k) {
                unsigned bh[2][4], bl[2][4];
#pragma unroll
                for (int jj = 0; jj < 2; ++jj) {
                    ldsm4t(bh[jj], whib + boff[k][jj]);
                    ldsm4t(bl[jj], wlob + boff[k][jj]);
                }
#pragma unroll
                for (int j = 0; j < 4; ++j) {
                    unsigned h0 = bh[j >> 1][(j & 1) * 2], h1 = bh[j >> 1][(j & 1) * 2 + 1];
                    unsigned l0 = bl[j >> 1][(j & 1) * 2], l1 = bl[j >> 1][(j & 1) * 2 + 1];
                    mma16816(acc[j], afh[k], h0, h1);
                    mma16816(acc[j], afl[k], h0, h1);
                    mma16816(acc[j], afh[k], l0, l1);
                }
            }

            const int ktb = t * BN + wnh * 32 + 2 * (lane & 3);
            const char* wnst = smem + A_WN(t & 1);
#pragma unroll
            for (int j = 0; j < 4; ++j) {
                float2 wn2 = *reinterpret_cast<const float2*>(wnst + wnidx + j * 32);
                int cb = ktb + j * 8;
#pragma unroll
                for (int sl = 0; sl < 2; ++sl) {
                    float s0 = fmaf(-2.0f, acc[j][sl * 2 + 0], wn2.x);
                    float s1 = fmaf(-2.0f, acc[j][sl * 2 + 1], wn2.y);
                    bool lt0 = s0 < best[sl];
                    float old0 = best[sl];
                    best[sl]  = lt0 ? s0 : old0;
                    best2[sl] = fminf(best2[sl], lt0 ? old0 : s0);
                    bk[sl]    = lt0 ? cb : bk[sl];
                    bool lt1 = s1 < best[sl];
                    float old1 = best[sl];
                    best[sl]  = lt1 ? s1 : old1;
                    best2[sl] = fminf(best2[sl], lt1 ? old1 : s1);
                    bk[sl]    = lt1 ? (cb + 1) : bk[sl];
                }
            }
            __syncthreads();
        }

#pragma unroll
        for (int off = 1; off <= 2; off <<= 1) {
#pragma unroll
            for (int s = 0; s < 2; ++s) {
                float ob  = __shfl_xor_sync(0xffffffffu, best[s], off);
                float ob2 = __shfl_xor_sync(0xffffffffu, best2[s], off);
                int   ok  = __shfl_xor_sync(0xffffffffu, bk[s], off);
                float nb2 = fminf(fminf(best2[s], ob2), fmaxf(best[s], ob));
                bool take = (ob < best[s]) || (ob == best[s] && ok < bk[s]);
                best[s] = take ? ob : best[s];
                bk[s]   = take ? ok : bk[s];
                best2[s] = nb2;
            }
        }

        float* mB  = reinterpret_cast<float*>(smem);
        float* mB2 = mB + 128;
        int*   mK  = reinterpret_cast<int*>(mB2 + 128);
        __syncthreads();
        if ((lane & 3) == 0) {
#pragma unroll
            for (int s = 0; s < 2; ++s) {
                int row = wm * 16 + (lane >> 2) + s * 8;
                mB [wnh * 32 + row] = best[s];
                mB2[wnh * 32 + row] = best2[s];
                mK [wnh * 32 + row] = bk[s];
            }
        }
        __syncthreads();
        if (tid < 32) {
            float nb = 3.4e38f; int nk = 0, ng = 0;
#pragma unroll
            for (int g = 0; g < 4; ++g) {
                float b = mB[g * 32 + tid];
                int   k = mK[g * 32 + tid];
                if (b < nb || (b == nb && k < nk)) { nb = b; nk = k; ng = g; }
            }
            float nb2 = 3.4e38f;
#pragma unroll
            for (int g = 0; g < 4; ++g) {
                float cand = (g == ng) ? mB2[g * 32 + tid]
                                       : fminf(mB[g * 32 + tid], mB2[g * 32 + tid]);
                nb2 = fminf(nb2, cand);
            }
            int li  = base + tid;
            int vid = avid[tid];
            bool valid = (li < namb);
            int k1 = g_bestk[vid];
            if (valid) g_bestk[vid] = nk;
            cOld[tid] = (valid && nk != k1) ? k1 : -1;
            cNew[tid] = nk;
            bool amb = valid && ((nb2 - nb) < MARGIN2);
            unsigned m = __ballot_sync(0xffffffffu, amb);
            int basep = 0;
            if (lane == 0 && m) basep = atomicAdd(&g_namb2, __popc(m));
            basep = __shfl_sync(0xffffffffu, basep, 0);
            if (amb) {
                int slot = basep + __popc(m & ((1u << lane) - 1u));
                g_amb2[slot] = vid;
                g_fixbest[slot] = 0xFFFFFFFFFFFFFFFFULL;
            }
        }
        __syncthreads();

#pragma unroll
        for (int j = 0; j < 4; ++j) {
            int r = wid * 4 + j;
            int kold = cOld[r];
            if (kold >= 0) {
                int vid  = avid[r];
                int knew = cNew[r];
                const float* xr = inputs + (size_t)(vid >> 12) * (CDIM * 4096) + (vid & 4095);
                float* qr = out + OFF_Q + (size_t)(vid >> 12) * (CDIM * 4096) + (vid & 4095);
                float ldelta = 0.0f;
#pragma unroll
                for (int h = 0; h < 2; ++h) {
                    int c = lane + h * 32;
                    float x  = xr[(size_t)c * 4096];
                    float wo = weight[(size_t)kold * CDIM + c];
                    float wn_ = weight[(size_t)knew * CDIM + c];
                    qr[(size_t)c * 4096] = wn_;
                    float dn = x - wn_, doo = x - wo;
                    ldelta += dn * dn - doo * doo;
                    atomicAdd(&g_dw[kold * CDIM + c], -x);
                    atomicAdd(&g_dw[knew * CDIM + c],  x);
                }
#pragma unroll
                for (int o = 16; o > 0; o >>= 1)
                    ldelta += __shfl_xor_sync(0xffffffffu, ldelta, o);
                if (lane == 0) {
                    atomicAdd(&g_loss, ldelta);
                    atomicAdd(&g_counts[kold], -1.0f);
                    atomicAdd(&g_counts[knew],  1.0f);
                    out[OFF_IDX + vid] = (float)knew;
                }
            }
        }
    }
}

// ---------------------------------------------------------------------------
// stage 3a: parallel exact fp32 scan
// ---------------------------------------------------------------------------
__global__ void fixup_scan_kernel(const float* __restrict__ inputs,
                                  const float* __restrict__ weight)
{
    __shared__ float xs[CDIM];
    __shared__ unsigned long long rmin[8];
    const int tid = threadIdx.x;
    const int namb2 = g_namb2;
    const int items = namb2 * FPARTS;

    for (int it = blockIdx.x; it < items; it += gridDim.x) {
        int li   = it >> 3;
        int part = it & 7;
        int v  = g_amb2[li];
        int bB = v >> 12, hw = v & 4095;
        __syncthreads();
        if (tid < CDIM)
            xs[tid] = inputs[(size_t)bB * (CDIM * 4096) + (size_t)tid * 4096 + hw];
        __syncthreads();

        float best = 3.4e38f; int bestk = 0;
#pragma unroll
        for (int q = 0; q < 2; ++q) {
            int k = part * 512 + q * 256 + tid;
            const float4* wr = reinterpret_cast<const float4*>(weight + (size_t)k * CDIM);
            float dot = 0.0f;
#pragma unroll
            for (int j = 0; j < 16; ++j) {
                float4 w4 = wr[j];
                dot = fmaf(xs[4 * j + 0], w4.x, dot);
                dot = fmaf(xs[4 * j + 1], w4.y, dot);
                dot = fmaf(xs[4 * j + 2], w4.z, dot);
                dot = fmaf(xs[4 * j + 3], w4.w, dot);
            }
            float s = fmaf(-2.0f, dot, g_wn[k]);
            if (s < best) { best = s; bestk = k; }
        }
        unsigned long long p =
            ((unsigned long long)encf(best) << 32) | (unsigned)bestk;
#pragma unroll
        for (int o = 16; o > 0; o >>= 1) {
            unsigned long long q2 = __shfl_xor_sync(0xffffffffu, p, o);
            p = (q2 < p) ? q2 : p;
        }
        if ((tid & 31) == 0) rmin[tid >> 5] = p;
        __syncthreads();
        if (tid == 0) {
            unsigned long long m = rmin[0];
#pragma unroll
            for (int w = 1; w < 8; ++w) m = (rmin[w] < m) ? rmin[w] : m;
            atomicMin(&g_fixbest[li], m);
        }
    }
}

// ---------------------------------------------------------------------------
// stage 3b: apply corrections
// ---------------------------------------------------------------------------
__global__ void fixup_apply_kernel(const float* __restrict__ inputs,
                                   const float* __restrict__ weight,
                                   float* __restrict__ out)
{
    const int tid = threadIdx.x;   // 64
    const int namb2 = g_namb2;

    for (int li = blockIdx.x; li < namb2; li += gridDim.x) {
        int v  = g_amb2[li];
        int bB = v >> 12, hw = v & 4095;
        int knew = (int)(unsigned)(g_fixbest[li] & 0xFFFFFFFFULL);
        int kold = g_bestk[v];
        if (knew != kold) {
            float x  = inputs[(size_t)bB * (CDIM * 4096) + (size_t)tid * 4096 + hw];
            float wo = weight[(size_t)kold * CDIM + tid];
            float wn_ = weight[(size_t)knew * CDIM + tid];
            out[OFF_Q + (size_t)bB * (CDIM * 4096) + (size_t)tid * 4096 + hw] = wn_;
            float dn = x - wn_, doo = x - wo;
            float ldelta = dn * dn - doo * doo;
            atomicAdd(&g_dw[kold * CDIM + tid], -x);
            atomicAdd(&g_dw[knew * CDIM + tid],  x);
#pragma unroll
            for (int o = 16; o > 0; o >>= 1)
                ldelta += __shfl_xor_sync(0xffffffffu, ldelta, o);
            if ((tid & 31) == 0) atomicAdd(&g_loss, ldelta);
            if (tid == 0) {
                atomicAdd(&g_counts[kold], -1.0f);
                atomicAdd(&g_counts[knew],  1.0f);
                out[OFF_IDX + v] = (float)knew;
            }
        }
    }
}

// ---------------------------------------------------------------------------
__global__ void finalize1_kernel(const float* __restrict__ ema_cs,
                                 float* __restrict__ out) {
    int k = blockIdx.x * blockDim.x + threadIdx.x;
    float ncs = 0.99f * ema_cs[k] + 0.01f * g_counts[k];
    out[OFF_CS + k] = ncs;
    float s = ncs;
#pragma unroll
    for (int o = 16; o > 0; o >>= 1)
        s += __shfl_xor_sync(0xffffffffu, s, o);
    __shared__ float sh[8];
    if ((threadIdx.x & 31) == 0) sh[threadIdx.x >> 5] = s;
    __syncthreads();
    if (threadIdx.x == 0) {
        float t = 0.0f;
#pragma unroll
        for (int w = 0; w < 8; ++w) t += sh[w];
        atomicAdd(&g_n, t);
    }
}

__global__ void finalize2_kernel(const float* __restrict__ ema_w,
                                 float* __restrict__ out) {
    int i = blockIdx.x * blockDim.x + threadIdx.x;
    int k = i >> 6;
    float n   = g_n;
    float ncs = out[OFF_CS + k];
    float cs  = (ncs + 1e-5f) / (n + (float)NUM_E * 1e-5f) * n;
    float ne  = 0.99f * ema_w[i] + 0.01f * g_dw[i];
    out[OFF_EW + i] = ne;
    out[OFF_W + i]  = ne / cs;
    if (i == 0) out[OFF_LOSS] = 0.25f * g_loss / 4194304.0f;
}

// ---------------------------------------------------------------------------
extern "C" void kernel_launch(void* const* d_in, const int* in_sizes, int n_in,
                              void* d_out, int out_size) {
    const float* inputs = (const float*)d_in[0];
    const float* weight = (const float*)d_in[1];
    const float* ema_cs = (const float*)d_in[2];
    const float* ema_w  = (const float*)d_in[3];
    float* out = (float*)d_out;

    cudaFuncSetAttribute(argmin_kernel,
                         cudaFuncAttributeMaxDynamicSharedMemorySize, SMEM_TOTAL);
    cudaFuncSetAttribute(amb_kernel,
                         cudaFuncAttributeMaxDynamicSharedMemorySize, A_SMEM);

    prep_zero_kernel<<<256, 256>>>();
    prep_wn_kernel<<<NUM_E / 256, 256>>>(weight);
    prep_cvt_kernel<<<NUM_E / 64, 256>>>(weight);
    argmin_kernel<<<NVEC / BM, THREADS, SMEM_TOTAL>>>(inputs, weight, out);  // 4th -> ncu
    amb_kernel<<<512, 256, A_SMEM>>>(inputs, weight, out);
    fixup_scan_kernel<<<4096, 256>>>(inputs, weight);
    fixup_apply_kernel<<<512, 64>>>(inputs, weight, out);
    finalize1_kernel<<<NUM_E / 256, 256>>>(ema_cs, out);
    finalize2_kernel<<<(NUM_E * CDIM) / 256, 256>>>(ema_w, out);
}

// round 14
// speedup vs baseline: 1.0351x; 1.0351x over previous
#include <cuda_runtime.h>
#include <cuda_fp16.h>

// ---------------------------------------------------------------------------
// EMA Vector Quantizer, round 14 (= R12 argmin + merged prep, trimmed tail):
//   prep: single kernel (transpose hi/lo + wn + zero)
//   stage 1: 1-pass fp16 HMMA argmin + scatter; BM=64, 2 CTAs/SM, m32 x n32
//   stage 2: 3-pass split-fp16 re-scan of ambiguous rows
//   stage 3: parallel exact fp32 scan + apply
// ---------------------------------------------------------------------------

#define NUM_E   4096
#define CDIM    64
#define NVEC    65536
#define BM      64
#define BN      128
#define NTILES  (NUM_E / BN)   // 32
#define THREADS 256
#define MARGIN1 0.09f
#define MARGIN2 1.0e-3f
#define FPARTS  8

#define OFF_Q    0
#define OFF_LOSS 4194304
#define OFF_IDX  4194305
#define OFF_W    (OFF_IDX + NVEC)
#define OFF_CS   (OFF_W + NUM_E * CDIM)
#define OFF_EW   (OFF_CS + NUM_E)

// stage-1 smem: X 8K + 2 x (W 16K + wn 512B)
#define SM_XH      0
#define SM_WBUF(b) (8192 + (b) * 16896)
#define SM_WN(b)   (SM_WBUF(b) + 16384)
#define SMEM_TOTAL (8192 + 2 * 16896)       // 41984

// stage-2 smem: 2 x (Whi 16K | Wlo 16K | wn .5K)
#define A_XH     0
#define A_XL     4096
#define A_VID    8192
#define A_COLD   8320
#define A_CNEW   8448
#define A_WB(b)  (9216 + (b) * 33280)
#define A_WLO(b) (A_WB(b) + 16384)
#define A_WN(b)  (A_WB(b) + 32768)
#define A_SMEM   (9216 + 2 * 33280)         // 75776

// device scratch
__device__ __half g_wth[CDIM * NUM_E];
__device__ __half g_wtl[CDIM * NUM_E];
__device__ float  g_wn[NUM_E];
__device__ float  g_counts[NUM_E];
__device__ float  g_dw[NUM_E * CDIM];
__device__ int    g_bestk[NVEC];
__device__ int    g_amb[NVEC];
__device__ int    g_namb;
__device__ int    g_amb2[NVEC];
__device__ int    g_namb2;
__device__ unsigned long long g_fixbest[NVEC];
__device__ float  g_loss;
__device__ float  g_n;

// ---- PTX helpers -----------------------------------------------------------
__device__ __forceinline__ unsigned smem_u32(const void* p) {
    return (unsigned)__cvta_generic_to_shared(p);
}
__device__ __forceinline__ void ldsm4(unsigned* r, unsigned addr) {
    asm volatile("ldmatrix.sync.aligned.m8n8.x4.shared.b16 {%0,%1,%2,%3}, [%4];"
                 : "=r"(r[0]), "=r"(r[1]), "=r"(r[2]), "=r"(r[3]) : "r"(addr));
}
__device__ __forceinline__ void ldsm4t(unsigned* r, unsigned addr) {
    asm volatile("ldmatrix.sync.aligned.m8n8.x4.trans.shared.b16 {%0,%1,%2,%3}, [%4];"
                 : "=r"(r[0]), "=r"(r[1]), "=r"(r[2]), "=r"(r[3]) : "r"(addr));
}
__device__ __forceinline__ void mma16816(float* c, const unsigned* a,
                                         unsigned b0, unsigned b1) {
    asm volatile("mma.sync.aligned.m16n8k16.row.col.f32.f16.f16.f32 "
                 "{%0,%1,%2,%3}, {%4,%5,%6,%7}, {%8,%9}, {%0,%1,%2,%3};"
                 : "+f"(c[0]), "+f"(c[1]), "+f"(c[2]), "+f"(c[3])
                 : "r"(a[0]), "r"(a[1]), "r"(a[2]), "r"(a[3]), "r"(b0), "r"(b1));
}
__device__ __forceinline__ void cpa16(unsigned dst, const void* src) {
    asm volatile("cp.async.cg.shared.global [%0], [%1], 16;"
                 :: "r"(dst), "l"(src) : "memory");
}
__device__ __forceinline__ unsigned encf(float f) {
    unsigned u = __float_as_uint(f);
    return (u & 0x80000000u) ? ~u : (u | 0x80000000u);
}

// ---------------------------------------------------------------------------
// prep (merged): tiled transpose hi/lo, wn, zero scratch  (grid 64, block 256)
// ---------------------------------------------------------------------------
__global__ void prep_kernel(const float* __restrict__ weight) {
    __shared__ float tile[64][65];
    const int tid = threadIdx.x;
    const int code0 = blockIdx.x * 64;

#pragma unroll
    for (int it = 0; it < 4; ++it) {
        int flat = it * 256 + tid;
        int code = flat >> 4, j = flat & 15;
        float4 v = reinterpret_cast<const float4*>(weight)[(size_t)(code0 + code) * 16 + j];
        tile[code][j * 4 + 0] = v.x;
        tile[code][j * 4 + 1] = v.y;
        tile[code][j * 4 + 2] = v.z;
        tile[code][j * 4 + 3] = v.w;
    }
    __syncthreads();

    if (tid < 64) {
        float s = 0.0f;
#pragma unroll
        for (int j = 0; j < 64; ++j) { float w = tile[tid][j]; s = fmaf(w, w, s); }
        g_wn[code0 + tid] = s;
        g_counts[code0 + tid] = 0.0f;
    }

#pragma unroll
    for (int it = 0; it < 16; ++it) {
        int flat = it * 256 + tid;
        int c = flat >> 6, code = flat & 63;
        float w = tile[code][c];
        __half hi = __float2half_rn(w);
        __half lo = __float2half_rn(w - __half2float(hi));
        g_wth[(size_t)c * NUM_E + code0 + code] = hi;
        g_wtl[(size_t)c * NUM_E + code0 + code] = lo;
    }

    float4 z = make_float4(0.f, 0.f, 0.f, 0.f);
#pragma unroll
    for (int it = 0; it < 4; ++it)
        reinterpret_cast<float4*>(g_dw)[blockIdx.x * 1024 + it * 256 + tid] = z;

    if (blockIdx.x == 0 && tid == 0) {
        g_loss = 0.0f; g_n = 0.0f; g_namb = 0; g_namb2 = 0;
    }
}

// ---------------------------------------------------------------------------
// stage 1 (fused): argmin + scatter; BM=64, 2 CTAs/SM, warp tile m32 x n32
// (R12 epilogue: select chains — proven fastest)
// ---------------------------------------------------------------------------
__global__ void __launch_bounds__(THREADS, 2)
argmin_kernel(const float* __restrict__ inputs,
              const float* __restrict__ weight,
              float* __restrict__ out)
{
    extern __shared__ char smem[];
    const unsigned sb = smem_u32(smem);
    const int tid  = threadIdx.x;
    const int lane = tid & 31;
    const int wid  = tid >> 5;
    const int wm   = wid >> 2;     // 0..1 (m32 slice)
    const int wnh  = wid & 3;      // 0..3 (n32 group)

    const int n0  = blockIdx.x * BM;
    const int bB  = n0 >> 12;
    const int hw0 = n0 & 4095;

    const float* xb = inputs + (size_t)bB * (CDIM * 4096) + hw0;
#pragma unroll
    for (int it = 0; it < 2; ++it) {
        int idx = it * 256 + tid;
        int c = (idx & 31) * 2;
        int r = (idx >> 5) * 4;
        float4 f0 = *reinterpret_cast<const float4*>(xb + (size_t)c * 4096 + r);
        float4 f1 = *reinterpret_cast<const float4*>(xb + (size_t)(c + 1) * 4096 + r);
        const float* p0 = &f0.x; const float* p1 = &f1.x;
#pragma unroll
        for (int q = 0; q < 4; ++q) {
            int row = r + q;
            unsigned off = row * 128 + (((c >> 3) ^ (row & 7)) * 16) + (c & 7) * 2;
            *reinterpret_cast<__half2*>(smem + SM_XH + off) =
                __floats2half2_rn(p0[q], p1[q]);
        }
    }
    __syncthreads();

    unsigned afh[2][4][4];
#pragma unroll
    for (int i = 0; i < 2; ++i)
#pragma unroll
        for (int k = 0; k < 4; ++k) {
            int row = wm * 32 + i * 16 + (lane & 15);
            int ch  = (k * 2 + (lane >> 4)) ^ (row & 7);
            ldsm4(afh[i][k], sb + SM_XH + row * 128 + ch * 16);
        }

    unsigned boff[4][2];
#pragma unroll
    for (int k = 0; k < 4; ++k)
#pragma unroll
        for (int jj = 0; jj < 2; ++jj) {
            int row = k * 16 + (lane & 15);
            int ch  = (wnh * 4 + jj * 2 + (lane >> 4)) ^ (row & 7);
            boff[k][jj] = row * 256 + ch * 16;
        }

    float best[4], best2[4]; int bk[4];
#pragma unroll
    for (int s = 0; s < 4; ++s) { best[s] = 3.4e38f; best2[s] = 3.4e38f; bk[s] = 0; }

    const int wnidx = (wnh * 32 + 2 * (lane & 3)) * 4;

    {
#pragma unroll
        for (int j = 0; j < 4; ++j) {
            int idx = j * 256 + tid;
            int row = idx >> 4, c = idx & 15;
            cpa16(sb + SM_WBUF(0) + row * 256 + ((c ^ (row & 7)) * 16),
                  g_wth + (size_t)row * NUM_E + c * 8);
        }
        if (tid < 32) cpa16(sb + SM_WN(0) + tid * 16, g_wn + tid * 4);
        asm volatile("cp.async.commit_group;" ::: "memory");
    }

    for (int t = 0; t < NTILES; ++t) {
        if (t + 1 < NTILES) {
            int kt = (t + 1) * BN, b = (t + 1) & 1;
#pragma unroll
            for (int j = 0; j < 4; ++j) {
                int idx = j * 256 + tid;
                int row = idx >> 4, c = idx & 15;
                cpa16(sb + SM_WBUF(b) + row * 256 + ((c ^ (row & 7)) * 16),
                      g_wth + (size_t)row * NUM_E + kt + c * 8);
            }
            if (tid < 32) cpa16(sb + SM_WN(b) + tid * 16, g_wn + kt + tid * 4);
            asm volatile("cp.async.commit_group;" ::: "memory");
            asm volatile("cp.async.wait_group 1;" ::: "memory");
        } else {
            asm volatile("cp.async.wait_group 0;" ::: "memory");
        }
        __syncthreads();

        const unsigned whib = sb + SM_WBUF(t & 1);
        float acc[2][4][4];
#pragma unroll
        for (int i = 0; i < 2; ++i)
#pragma unroll
            for (int j = 0; j < 4; ++j)
#pragma unroll
                for (int e = 0; e < 4; ++e) acc[i][j][e] = 0.0f;

#pragma unroll
        for (int k = 0; k < 4; ++k) {
            unsigned bh[2][4];
#pragma unroll
            for (int jj = 0; jj < 2; ++jj) ldsm4t(bh[jj], whib + boff[k][jj]);
#pragma unroll
            for (int i = 0; i < 2; ++i)
#pragma unroll
                for (int j = 0; j < 4; ++j)
                    mma16816(acc[i][j], afh[i][k], bh[j >> 1][(j & 1) * 2],
                             bh[j >> 1][(j & 1) * 2 + 1]);
        }

        const int ktb = t * BN + wnh * 32 + 2 * (lane & 3);
        const char* wnst = smem + SM_WN(t & 1);
#pragma unroll
        for (int j = 0; j < 4; ++j) {
            float2 wn2 = *reinterpret_cast<const float2*>(wnst + wnidx + j * 32);
            int cb = ktb + j * 8;
#pragma unroll
            for (int i = 0; i < 2; ++i) {
#pragma unroll
                for (int hlf = 0; hlf < 2; ++hlf) {
                    int sl = i * 2 + hlf;
                    float s0 = fmaf(-2.0f, acc[i][j][hlf * 2 + 0], wn2.x);
                    float s1 = fmaf(-2.0f, acc[i][j][hlf * 2 + 1], wn2.y);
                    bool lt0 = s0 < best[sl];
                    float old0 = best[sl];
                    best[sl]  = lt0 ? s0 : old0;
                    best2[sl] = fminf(best2[sl], lt0 ? old0 : s0);
                    bk[sl]    = lt0 ? cb : bk[sl];
                    bool lt1 = s1 < best[sl];
                    float old1 = best[sl];
                    best[sl]  = lt1 ? s1 : old1;
                    best2[sl] = fminf(best2[sl], lt1 ? old1 : s1);
                    bk[sl]    = lt1 ? (cb + 1) : bk[sl];
                }
            }
        }
        __syncthreads();
    }

    // quad reduction
#pragma unroll
    for (int off = 1; off <= 2; off <<= 1) {
#pragma unroll
        for (int s = 0; s < 4; ++s) {
            float ob  = __shfl_xor_sync(0xffffffffu, best[s], off);
            float ob2 = __shfl_xor_sync(0xffffffffu, best2[s], off);
            int   ok  = __shfl_xor_sync(0xffffffffu, bk[s], off);
            float nb2 = fminf(fminf(best2[s], ob2), fmaxf(best[s], ob));
            bool take = (ob < best[s]) || (ob == best[s] && ok < bk[s]);
            best[s] = take ? ob : best[s];
            bk[s]   = take ? ok : bk[s];
            best2[s] = nb2;
        }
    }

    // stage per (row, n-group), merge 4 groups
    float* mB  = reinterpret_cast<float*>(smem);          // [4][64]
    float* mB2 = mB + 256;
    int*   mK  = reinterpret_cast<int*>(mB2 + 256);
    int*   idx_s = mK + 256;                               // [64]
    float* red   = reinterpret_cast<float*>(idx_s + 64);   // [8]
    __syncthreads();
    if ((lane & 3) == 0) {
#pragma unroll
        for (int s = 0; s < 4; ++s) {
            int row = wm * 32 + (s >> 1) * 16 + (lane >> 2) + (s & 1) * 8;
            mB [wnh * 64 + row] = best[s];
            mB2[wnh * 64 + row] = best2[s];
            mK [wnh * 64 + row] = bk[s];
        }
    }
    __syncthreads();
    if (tid < 64) {
        float nb = 3.4e38f; int nk = 0, ng = 0;
#pragma unroll
        for (int g = 0; g < 4; ++g) {
            float b = mB[g * 64 + tid];
            int   k = mK[g * 64 + tid];
            if (b < nb || (b == nb && k < nk)) { nb = b; nk = k; ng = g; }
        }
        float nb2 = 3.4e38f;
#pragma unroll
        for (int g = 0; g < 4; ++g) {
            float cand = (g == ng) ? mB2[g * 64 + tid]
                                   : fminf(mB[g * 64 + tid], mB2[g * 64 + tid]);
            nb2 = fminf(nb2, cand);
        }
        g_bestk[n0 + tid] = nk;
        idx_s[tid] = nk;
        out[OFF_IDX + n0 + tid] = (float)nk;
        atomicAdd(&g_counts[nk], 1.0f);
        bool amb = (nb2 - nb) < MARGIN1;
        unsigned m = __ballot_sync(0xffffffffu, amb);
        int basep = 0;
        if (lane == 0 && m) basep = atomicAdd(&g_namb, __popc(m));
        basep = __shfl_sync(0xffffffffu, basep, 0);
        if (amb) g_amb[basep + __popc(m & ((1u << lane) - 1u))] = n0 + tid;
    }
    __syncthreads();

    // fused scatter
    float* outq = out + OFF_Q + (size_t)bB * (CDIM * 4096) + hw0;
    float lsum = 0.0f;
#pragma unroll
    for (int it = 0; it < 4; ++it) {
        int u  = it * 256 + tid;
        int c  = u >> 4;
        int r4 = (u & 15) * 4;
        float4 x4 = *reinterpret_cast<const float4*>(xb + (size_t)c * 4096 + r4);
        int k0i = idx_s[r4 + 0], k1i = idx_s[r4 + 1];
        int k2i = idx_s[r4 + 2], k3i = idx_s[r4 + 3];
        float q0 = __ldg(weight + (size_t)k0i * CDIM + c);
        float q1 = __ldg(weight + (size_t)k1i * CDIM + c);
        float q2 = __ldg(weight + (size_t)k2i * CDIM + c);
        float q3 = __ldg(weight + (size_t)k3i * CDIM + c);
        *reinterpret_cast<float4*>(outq + (size_t)c * 4096 + r4) =
            make_float4(q0, q1, q2, q3);
        float d0 = x4.x - q0, d1 = x4.y - q1, d2 = x4.z - q2, d3 = x4.w - q3;
        lsum += d0 * d0 + d1 * d1 + d2 * d2 + d3 * d3;
        atomicAdd(&g_dw[k0i * CDIM + c], x4.x);
        atomicAdd(&g_dw[k1i * CDIM + c], x4.y);
        atomicAdd(&g_dw[k2i * CDIM + c], x4.z);
        atomicAdd(&g_dw[k3i * CDIM + c], x4.w);
    }
#pragma unroll
    for (int o = 16; o > 0; o >>= 1)
        lsum += __shfl_xor_sync(0xffffffffu, lsum, o);
    if (lane == 0) red[wid] = lsum;
    __syncthreads();
    if (tid == 0) {
        float s = 0.0f;
#pragma unroll
        for (int w = 0; w < 8; ++w) s += red[w];
        atomicAdd(&g_loss, s);
    }
}

// ---------------------------------------------------------------------------
// stage 2: 3-pass split-fp16 re-scan of ambiguous rows + in-place corrections
// ---------------------------------------------------------------------------
__global__ void __launch_bounds__(256, 1)
amb_kernel(const float* __restrict__ inputs,
           const float* __restrict__ weight,
           float* __restrict__ out)
{
    extern __shared__ char smem[];
    const unsigned sb = smem_u32(smem);
    const int tid  = threadIdx.x;
    const int lane = tid & 31;
    const int wid  = tid >> 5;
    const int wm   = wid >> 2;
    const int wnh  = wid & 3;

    const int namb = g_namb;
    if (namb == 0) return;

    int* avid = reinterpret_cast<int*>(smem + A_VID);
    int* cOld = reinterpret_cast<int*>(smem + A_COLD);
    int* cNew = reinterpret_cast<int*>(smem + A_CNEW);

    unsigned boff[4][2];
#pragma unroll
    for (int k = 0; k < 4; ++k)
#pragma unroll
        for (int jj = 0; jj < 2; ++jj) {
            int row = k * 16 + (lane & 15);
            int ch  = (wnh * 4 + jj * 2 + (lane >> 4)) ^ (row & 7);
            boff[k][jj] = row * 256 + ch * 16;
        }
    const int wnidx = (wnh * 32 + 2 * (lane & 3)) * 4;

    for (int base = blockIdx.x * 32; base < namb; base += gridDim.x * 32) {
        __syncthreads();

        if (tid < 32) {
            int li = base + tid;
            avid[tid] = g_amb[li < namb ? li : (namb - 1)];
        }
        __syncthreads();

        {
            int r = tid >> 3;
            int c0 = (tid & 7) * 8;
            int vid = avid[r];
            const float* xr = inputs + (size_t)(vid >> 12) * (CDIM * 4096) + (vid & 4095);
#pragma unroll
            for (int q = 0; q < 8; ++q) {
                int c = c0 + q;
                float v = xr[(size_t)c * 4096];
                __half hi = __float2half_rn(v);
                __half lo = __float2half_rn(v - __half2float(hi));
                unsigned off = r * 128 + (((c >> 3) ^ (r & 7)) * 16) + (c & 7) * 2;
                *reinterpret_cast<__half*>(smem + A_XH + off) = hi;
                *reinterpret_cast<__half*>(smem + A_XL + off) = lo;
            }
        }
        __syncthreads();

        unsigned afh[4][4], afl[4][4];
#pragma unroll
        for (int k = 0; k < 4; ++k) {
            int row = wm * 16 + (lane & 15);
            int ch  = (k * 2 + (lane >> 4)) ^ (row & 7);
            ldsm4(afh[k], sb + A_XH + row * 128 + ch * 16);
            ldsm4(afl[k], sb + A_XL + row * 128 + ch * 16);
        }

        float best[2], best2[2]; int bk[2];
#pragma unroll
        for (int s = 0; s < 2; ++s) { best[s] = 3.4e38f; best2[s] = 3.4e38f; bk[s] = 0; }

        {
#pragma unroll
            for (int j = 0; j < 4; ++j) {
                int idx = j * 256 + tid;
                int row = idx >> 4, c = idx & 15;
                unsigned dsw = row * 256 + ((c ^ (row & 7)) * 16);
                cpa16(sb + A_WB(0)  + dsw, g_wth + (size_t)row * NUM_E + c * 8);
                cpa16(sb + A_WLO(0) + dsw, g_wtl + (size_t)row * NUM_E + c * 8);
            }
            if (tid < 32) cpa16(sb + A_WN(0) + tid * 16, g_wn + tid * 4);
            asm volatile("cp.async.commit_group;" ::: "memory");
        }

        for (int t = 0; t < NTILES; ++t) {
            if (t + 1 < NTILES) {
                int kt = (t + 1) * BN, b = (t + 1) & 1;
#pragma unroll
                for (int j = 0; j < 4; ++j) {
                    int idx = j * 256 + tid;
                    int row = idx >> 4, c = idx & 15;
                    unsigned dsw = row * 256 + ((c ^ (row & 7)) * 16);
                    cpa16(sb + A_WB(b)  + dsw, g_wth + (size_t)row * NUM_E + kt + c * 8);
                    cpa16(sb + A_WLO(b) + dsw, g_wtl + (size_t)row * NUM_E + kt + c * 8);
                }
                if (tid < 32) cpa16(sb + A_WN(b) + tid * 16, g_wn + kt + tid * 4);
                asm volatile("cp.async.commit_group;" ::: "memory");
                asm volatile("cp.async.wait_group 1;" ::: "memory");
            } else {
                asm volatile("cp.async.wait_group 0;" ::: "memory");
            }
            __syncthreads();

            const unsigned whib = sb + A_WB(t & 1);
            const unsigned wlob = sb + A_WLO(t & 1);
            float acc[4][4];
#pragma unroll
            for (int j = 0; j < 4; ++j)
#pragma unroll
                for (int e = 0; e < 4; ++e) acc[j][e] = 0.0f;

#pragma unroll
            for (int k = 0; k < 4; ++k) {
                unsigned bh[2][4], bl[2][4];
#pragma unroll
                for (int jj = 0; jj < 2; ++jj) {
                    ldsm4t(bh[jj], whib + boff[k][jj]);
                    ldsm4t(bl[jj], wlob + boff[k][jj]);
                }
#pragma unroll
                for (int j = 0; j < 4; ++j) {
                    unsigned h0 = bh[j >> 1][(j & 1) * 2], h1 = bh[j >> 1][(j & 1) * 2 + 1];
                    unsigned l0 = bl[j >> 1][(j & 1) * 2], l1 = bl[j >> 1][(j & 1) * 2 + 1];
                    mma16816(acc[j], afh[k], h0, h1);
                    mma16816(acc[j], afl[k], h0, h1);
                    mma16816(acc[j], afh[k], l0, l1);
                }
            }

            const int ktb = t * BN + wnh * 32 + 2 * (lane & 3);
            const char* wnst = smem + A_WN(t & 1);
#pragma unroll
            for (int j = 0; j < 4; ++j) {
                float2 wn2 = *reinterpret_cast<const float2*>(wnst + wnidx + j * 32);
                int cb = ktb + j * 8;
#pragma unroll
                for (int sl = 0; sl < 2; ++sl) {
                    float s0 = fmaf(-2.0f, acc[j][sl * 2 + 0], wn2.x);
                    float s1 = fmaf(-2.0f, acc[j][sl * 2 + 1], wn2.y);
                    bool lt0 = s0 < best[sl];
                    float old0 = best[sl];
                    best[sl]  = lt0 ? s0 : old0;
                    best2[sl] = fminf(best2[sl], lt0 ? old0 : s0);
                    bk[sl]    = lt0 ? cb : bk[sl];
                    bool lt1 = s1 < best[sl];
                    float old1 = best[sl];
                    best[sl]  = lt1 ? s1 : old1;
                    best2[sl] = fminf(best2[sl], lt1 ? old1 : s1);
                    bk[sl]    = lt1 ? (cb + 1) : bk[sl];
                }
            }
            __syncthreads();
        }

#pragma unroll
        for (int off = 1; off <= 2; off <<= 1) {
#pragma unroll
            for (int s = 0; s < 2; ++s) {
                float ob  = __shfl_xor_sync(0xffffffffu, best[s], off);
                float ob2 = __shfl_xor_sync(0xffffffffu, best2[s], off);
                int   ok  = __shfl_xor_sync(0xffffffffu, bk[s], off);
                float nb2 = fminf(fminf(best2[s], ob2), fmaxf(best[s], ob));
                bool take = (ob < best[s]) || (ob == best[s] && ok < bk[s]);
                best[s] = take ? ob : best[s];
                bk[s]   = take ? ok : bk[s];
                best2[s] = nb2;
            }
        }

        float* mB  = reinterpret_cast<float*>(smem);
        float* mB2 = mB + 128;
        int*   mK  = reinterpret_cast<int*>(mB2 + 128);
        __syncthreads();
        if ((lane & 3) == 0) {
#pragma unroll
            for (int s = 0; s < 2; ++s) {
                int row = wm * 16 + (lane >> 2) + s * 8;
                mB [wnh * 32 + row] = best[s];
                mB2[wnh * 32 + row] = best2[s];
                mK [wnh * 32 + row] = bk[s];
            }
        }
        __syncthreads();
        if (tid < 32) {
            float nb = 3.4e38f; int nk = 0, ng = 0;
#pragma unroll
            for (int g = 0; g < 4; ++g) {
                float b = mB[g * 32 + tid];
                int   k = mK[g * 32 + tid];
                if (b < nb || (b == nb && k < nk)) { nb = b; nk = k; ng = g; }
            }
            float nb2 = 3.4e38f;
#pragma unroll
            for (int g = 0; g < 4; ++g) {
                float cand = (g == ng) ? mB2[g * 32 + tid]
                                       : fminf(mB[g * 32 + tid], mB2[g * 32 + tid]);
                nb2 = fminf(nb2, cand);
            }
            int li  = base + tid;
            int vid = avid[tid];
            bool valid = (li < namb);
            int k1 = g_bestk[vid];
            if (valid) g_bestk[vid] = nk;
            cOld[tid] = (valid && nk != k1) ? k1 : -1;
            cNew[tid] = nk;
            bool amb = valid && ((nb2 - nb) < MARGIN2);
            unsigned m = __ballot_sync(0xffffffffu, amb);
            int basep = 0;
            if (lane == 0 && m) basep = atomicAdd(&g_namb2, __popc(m));
            basep = __shfl_sync(0xffffffffu, basep, 0);
            if (amb) {
                int slot = basep + __popc(m & ((1u << lane) - 1u));
                g_amb2[slot] = vid;
                g_fixbest[slot] = 0xFFFFFFFFFFFFFFFFULL;
            }
        }
        __syncthreads();

#pragma unroll
        for (int j = 0; j < 4; ++j) {
            int r = wid * 4 + j;
            int kold = cOld[r];
            if (kold >= 0) {
                int vid  = avid[r];
                int knew = cNew[r];
                const float* xr = inputs + (size_t)(vid >> 12) * (CDIM * 4096) + (vid & 4095);
                float* qr = out + OFF_Q + (size_t)(vid >> 12) * (CDIM * 4096) + (vid & 4095);
                float ldelta = 0.0f;
#pragma unroll
                for (int h = 0; h < 2; ++h) {
                    int c = lane + h * 32;
                    float x  = xr[(size_t)c * 4096];
                    float wo = weight[(size_t)kold * CDIM + c];
                    float wn_ = weight[(size_t)knew * CDIM + c];
                    qr[(size_t)c * 4096] = wn_;
                    float dn = x - wn_, doo = x - wo;
                    ldelta += dn * dn - doo * doo;
                    atomicAdd(&g_dw[kold * CDIM + c], -x);
                    atomicAdd(&g_dw[knew * CDIM + c],  x);
                }
#pragma unroll
                for (int o = 16; o > 0; o >>= 1)
                    ldelta += __shfl_xor_sync(0xffffffffu, ldelta, o);
                if (lane == 0) {
                    atomicAdd(&g_loss, ldelta);
                    atomicAdd(&g_counts[kold], -1.0f);
                    atomicAdd(&g_counts[knew],  1.0f);
                    out[OFF_IDX + vid] = (float)knew;
                }
            }
        }
    }
}

// ---------------------------------------------------------------------------
// stage 3a: parallel exact fp32 scan
// ---------------------------------------------------------------------------
__global__ void fixup_scan_kernel(const float* __restrict__ inputs,
                                  const float* __restrict__ weight)
{
    __shared__ float xs[CDIM];
    __shared__ unsigned long long rmin[8];
    const int tid = threadIdx.x;
    const int namb2 = g_namb2;
    const int items = namb2 * FPARTS;

    for (int it = blockIdx.x; it < items; it += gridDim.x) {
        int li   = it >> 3;
        int part = it & 7;
        int v  = g_amb2[li];
        int bB = v >> 12, hw = v & 4095;
        __syncthreads();
        if (tid < CDIM)
            xs[tid] = inputs[(size_t)bB * (CDIM * 4096) + (size_t)tid * 4096 + hw];
        __syncthreads();

        float best = 3.4e38f; int bestk = 0;
#pragma unroll
        for (int q = 0; q < 2; ++q) {
            int k = part * 512 + q * 256 + tid;
            const float4* wr = reinterpret_cast<const float4*>(weight + (size_t)k * CDIM);
            float dot = 0.0f;
#pragma unroll
            for (int j = 0; j < 16; ++j) {
                float4 w4 = wr[j];
                dot = fmaf(xs[4 * j + 0], w4.x, dot);
                dot = fmaf(xs[4 * j + 1], w4.y, dot);
                dot = fmaf(xs[4 * j + 2], w4.z, dot);
                dot = fmaf(xs[4 * j + 3], w4.w, dot);
            }
            float s = fmaf(-2.0f, dot, g_wn[k]);
            if (s < best) { best = s; bestk = k; }
        }
        unsigned long long p =
            ((unsigned long long)encf(best) << 32) | (unsigned)bestk;
#pragma unroll
        for (int o = 16; o > 0; o >>= 1) {
            unsigned long long q2 = __shfl_xor_sync(0xffffffffu, p, o);
            p = (q2 < p) ? q2 : p;
        }
        if ((tid & 31) == 0) rmin[tid >> 5] = p;
        __syncthreads();
        if (tid == 0) {
            unsigned long long m = rmin[0];
#pragma unroll
            for (int w = 1; w < 8; ++w) m = (rmin[w] < m) ? rmin[w] : m;
            atomicMin(&g_fixbest[li], m);
        }
    }
}

// ---------------------------------------------------------------------------
// stage 3b: apply corrections
// ---------------------------------------------------------------------------
__global__ void fixup_apply_kernel(const float* __restrict__ inputs,
                                   const float* __restrict__ weight,
                                   float* __restrict__ out)
{
    const int tid = threadIdx.x;   // 64
    const int namb2 = g_namb2;

    for (int li = blockIdx.x; li < namb2; li += gridDim.x) {
        int v  = g_amb2[li];
        int bB = v >> 12, hw = v & 4095;
        int knew = (int)(unsigned)(g_fixbest[li] & 0xFFFFFFFFULL);
        int kold = g_bestk[v];
        if (knew != kold) {
            float x  = inputs[(size_t)bB * (CDIM * 4096) + (size_t)tid * 4096 + hw];
            float wo = weight[(size_t)kold * CDIM + tid];
            float wn_ = weight[(size_t)knew * CDIM + tid];
            out[OFF_Q + (size_t)bB * (CDIM * 4096) + (size_t)tid * 4096 + hw] = wn_;
            float dn = x - wn_, doo = x - wo;
            float ldelta = dn * dn - doo * doo;
            atomicAdd(&g_dw[kold * CDIM + tid], -x);
            atomicAdd(&g_dw[knew * CDIM + tid],  x);
#pragma unroll
            for (int o = 16; o > 0; o >>= 1)
                ldelta += __shfl_xor_sync(0xffffffffu, ldelta, o);
            if ((tid & 31) == 0) atomicAdd(&g_loss, ldelta);
            if (tid == 0) {
                atomicAdd(&g_counts[kold], -1.0f);
                atomicAdd(&g_counts[knew],  1.0f);
                out[OFF_IDX + v] = (float)knew;
            }
        }
    }
}

// ---------------------------------------------------------------------------
__global__ void finalize1_kernel(const float* __restrict__ ema_cs,
                                 float* __restrict__ out) {
    int k = blockIdx.x * blockDim.x + threadIdx.x;
    float ncs = 0.99f * ema_cs[k] + 0.01f * g_counts[k];
    out[OFF_CS + k] = ncs;
    float s = ncs;
#pragma unroll
    for (int o = 16; o > 0; o >>= 1)
        s += __shfl_xor_sync(0xffffffffu, s, o);
    __shared__ float sh[8];
    if ((threadIdx.x & 31) == 0) sh[threadIdx.x >> 5] = s;
    __syncthreads();
    if (threadIdx.x == 0) {
        float t = 0.0f;
#pragma unroll
        for (int w = 0; w < 8; ++w) t += sh[w];
        atomicAdd(&g_n, t);
    }
}

__global__ void finalize2_kernel(const float* __restrict__ ema_w,
                                 float* __restrict__ out) {
    int i = blockIdx.x * blockDim.x + threadIdx.x;
    int k = i >> 6;
    float n   = g_n;
    float ncs = out[OFF_CS + k];
    float cs  = (ncs + 1e-5f) / (n + (float)NUM_E * 1e-5f) * n;
    float ne  = 0.99f * ema_w[i] + 0.01f * g_dw[i];
    out[OFF_EW + i] = ne;
    out[OFF_W + i]  = ne / cs;
    if (i == 0) out[OFF_LOSS] = 0.25f * g_loss / 4194304.0f;
}

// ---------------------------------------------------------------------------
extern "C" void kernel_launch(void* const* d_in, const int* in_sizes, int n_in,
                              void* d_out, int out_size) {
    const float* inputs = (const float*)d_in[0];
    const float* weight = (const float*)d_in[1];
    const float* ema_cs = (const float*)d_in[2];
    const float* ema_w  = (const float*)d_in[3];
    float* out = (float*)d_out;

    cudaFuncSetAttribute(argmin_kernel,
                         cudaFuncAttributeMaxDynamicSharedMemorySize, SMEM_TOTAL);
    cudaFuncSetAttribute(amb_kernel,
                         cudaFuncAttributeMaxDynamicSharedMemorySize, A_SMEM);

    prep_kernel<<<NUM_E / 64, 256>>>(weight);
    argmin_kernel<<<NVEC / BM, THREADS, SMEM_TOTAL>>>(inputs, weight, out);
    amb_kernel<<<512, 256, A_SMEM>>>(inputs, weight, out);
    fixup_scan_kernel<<<2048, 256>>>(inputs, weight);
    fixup_apply_kernel<<<512, 64>>>(inputs, weight, out);
    finalize1_kernel<<<NUM_E / 256, 256>>>(ema_cs, out);
    finalize2_kernel<<<(NUM_E * CDIM) / 256, 256>>>(ema_w, out);
}

// round 15
// speedup vs baseline: 1.0572x; 1.0214x over previous
#include <cuda_runtime.h>
#include <cuda_fp16.h>

// ---------------------------------------------------------------------------
// EMA Vector Quantizer, round 15 (= R14 + fused fixup scan/apply, FPARTS=16):
//   prep: single kernel (transpose hi/lo + wn + zero)
//   stage 1: 1-pass fp16 HMMA argmin + scatter; BM=64, 2 CTAs/SM, m32 x n32
//   stage 2: 3-pass split-fp16 re-scan of ambiguous rows
//   stage 3: parallel exact fp32 scan with in-block apply on last-part finish
// ---------------------------------------------------------------------------

#define NUM_E   4096
#define CDIM    64
#define NVEC    65536
#define BM      64
#define BN      128
#define NTILES  (NUM_E / BN)   // 32
#define THREADS 256
#define MARGIN1 0.09f
#define MARGIN2 1.0e-3f
#define FPARTS  16

#define OFF_Q    0
#define OFF_LOSS 4194304
#define OFF_IDX  4194305
#define OFF_W    (OFF_IDX + NVEC)
#define OFF_CS   (OFF_W + NUM_E * CDIM)
#define OFF_EW   (OFF_CS + NUM_E)

// stage-1 smem: X 8K + 2 x (W 16K + wn 512B)
#define SM_XH      0
#define SM_WBUF(b) (8192 + (b) * 16896)
#define SM_WN(b)   (SM_WBUF(b) + 16384)
#define SMEM_TOTAL (8192 + 2 * 16896)       // 41984

// stage-2 smem: 2 x (Whi 16K | Wlo 16K | wn .5K)
#define A_XH     0
#define A_XL     4096
#define A_VID    8192
#define A_COLD   8320
#define A_CNEW   8448
#define A_WB(b)  (9216 + (b) * 33280)
#define A_WLO(b) (A_WB(b) + 16384)
#define A_WN(b)  (A_WB(b) + 32768)
#define A_SMEM   (9216 + 2 * 33280)         // 75776

// device scratch
__device__ __half g_wth[CDIM * NUM_E];
__device__ __half g_wtl[CDIM * NUM_E];
__device__ float  g_wn[NUM_E];
__device__ float  g_counts[NUM_E];
__device__ float  g_dw[NUM_E * CDIM];
__device__ int    g_bestk[NVEC];
__device__ int    g_amb[NVEC];
__device__ int    g_namb;
__device__ int    g_amb2[NVEC];
__device__ int    g_namb2;
__device__ unsigned long long g_fixbest[NVEC];
__device__ int    g_fixcnt[NVEC];
__device__ float  g_loss;
__device__ float  g_n;

// ---- PTX helpers -----------------------------------------------------------
__device__ __forceinline__ unsigned smem_u32(const void* p) {
    return (unsigned)__cvta_generic_to_shared(p);
}
__device__ __forceinline__ void ldsm4(unsigned* r, unsigned addr) {
    asm volatile("ldmatrix.sync.aligned.m8n8.x4.shared.b16 {%0,%1,%2,%3}, [%4];"
                 : "=r"(r[0]), "=r"(r[1]), "=r"(r[2]), "=r"(r[3]) : "r"(addr));
}
__device__ __forceinline__ void ldsm4t(unsigned* r, unsigned addr) {
    asm volatile("ldmatrix.sync.aligned.m8n8.x4.trans.shared.b16 {%0,%1,%2,%3}, [%4];"
                 : "=r"(r[0]), "=r"(r[1]), "=r"(r[2]), "=r"(r[3]) : "r"(addr));
}
__device__ __forceinline__ void mma16816(float* c, const unsigned* a,
                                         unsigned b0, unsigned b1) {
    asm volatile("mma.sync.aligned.m16n8k16.row.col.f32.f16.f16.f32 "
                 "{%0,%1,%2,%3}, {%4,%5,%6,%7}, {%8,%9}, {%0,%1,%2,%3};"
                 : "+f"(c[0]), "+f"(c[1]), "+f"(c[2]), "+f"(c[3])
                 : "r"(a[0]), "r"(a[1]), "r"(a[2]), "r"(a[3]), "r"(b0), "r"(b1));
}
__device__ __forceinline__ void cpa16(unsigned dst, const void* src) {
    asm volatile("cp.async.cg.shared.global [%0], [%1], 16;"
                 :: "r"(dst), "l"(src) : "memory");
}
__device__ __forceinline__ unsigned encf(float f) {
    unsigned u = __float_as_uint(f);
    return (u & 0x80000000u) ? ~u : (u | 0x80000000u);
}

// ---------------------------------------------------------------------------
// prep (merged): tiled transpose hi/lo, wn, zero scratch  (grid 64, block 256)
// ---------------------------------------------------------------------------
__global__ void prep_kernel(const float* __restrict__ weight) {
    __shared__ float tile[64][65];
    const int tid = threadIdx.x;
    const int code0 = blockIdx.x * 64;

#pragma unroll
    for (int it = 0; it < 4; ++it) {
        int flat = it * 256 + tid;
        int code = flat >> 4, j = flat & 15;
        float4 v = reinterpret_cast<const float4*>(weight)[(size_t)(code0 + code) * 16 + j];
        tile[code][j * 4 + 0] = v.x;
        tile[code][j * 4 + 1] = v.y;
        tile[code][j * 4 + 2] = v.z;
        tile[code][j * 4 + 3] = v.w;
    }
    __syncthreads();

    if (tid < 64) {
        float s = 0.0f;
#pragma unroll
        for (int j = 0; j < 64; ++j) { float w = tile[tid][j]; s = fmaf(w, w, s); }
        g_wn[code0 + tid] = s;
        g_counts[code0 + tid] = 0.0f;
    }

#pragma unroll
    for (int it = 0; it < 16; ++it) {
        int flat = it * 256 + tid;
        int c = flat >> 6, code = flat & 63;
        float w = tile[code][c];
        __half hi = __float2half_rn(w);
        __half lo = __float2half_rn(w - __half2float(hi));
        g_wth[(size_t)c * NUM_E + code0 + code] = hi;
        g_wtl[(size_t)c * NUM_E + code0 + code] = lo;
    }

    float4 z = make_float4(0.f, 0.f, 0.f, 0.f);
#pragma unroll
    for (int it = 0; it < 4; ++it)
        reinterpret_cast<float4*>(g_dw)[blockIdx.x * 1024 + it * 256 + tid] = z;

    if (blockIdx.x == 0 && tid == 0) {
        g_loss = 0.0f; g_n = 0.0f; g_namb = 0; g_namb2 = 0;
    }
}

// ---------------------------------------------------------------------------
// stage 1 (fused): argmin + scatter; BM=64, 2 CTAs/SM, warp tile m32 x n32
// ---------------------------------------------------------------------------
__global__ void __launch_bounds__(THREADS, 2)
argmin_kernel(const float* __restrict__ inputs,
              const float* __restrict__ weight,
              float* __restrict__ out)
{
    extern __shared__ char smem[];
    const unsigned sb = smem_u32(smem);
    const int tid  = threadIdx.x;
    const int lane = tid & 31;
    const int wid  = tid >> 5;
    const int wm   = wid >> 2;     // 0..1 (m32 slice)
    const int wnh  = wid & 3;      // 0..3 (n32 group)

    const int n0  = blockIdx.x * BM;
    const int bB  = n0 >> 12;
    const int hw0 = n0 & 4095;

    const float* xb = inputs + (size_t)bB * (CDIM * 4096) + hw0;
#pragma unroll
    for (int it = 0; it < 2; ++it) {
        int idx = it * 256 + tid;
        int c = (idx & 31) * 2;
        int r = (idx >> 5) * 4;
        float4 f0 = *reinterpret_cast<const float4*>(xb + (size_t)c * 4096 + r);
        float4 f1 = *reinterpret_cast<const float4*>(xb + (size_t)(c + 1) * 4096 + r);
        const float* p0 = &f0.x; const float* p1 = &f1.x;
#pragma unroll
        for (int q = 0; q < 4; ++q) {
            int row = r + q;
            unsigned off = row * 128 + (((c >> 3) ^ (row & 7)) * 16) + (c & 7) * 2;
            *reinterpret_cast<__half2*>(smem + SM_XH + off) =
                __floats2half2_rn(p0[q], p1[q]);
        }
    }
    __syncthreads();

    unsigned afh[2][4][4];
#pragma unroll
    for (int i = 0; i < 2; ++i)
#pragma unroll
        for (int k = 0; k < 4; ++k) {
            int row = wm * 32 + i * 16 + (lane & 15);
            int ch  = (k * 2 + (lane >> 4)) ^ (row & 7);
            ldsm4(afh[i][k], sb + SM_XH + row * 128 + ch * 16);
        }

    unsigned boff[4][2];
#pragma unroll
    for (int k = 0; k < 4; ++k)
#pragma unroll
        for (int jj = 0; jj < 2; ++jj) {
            int row = k * 16 + (lane & 15);
            int ch  = (wnh * 4 + jj * 2 + (lane >> 4)) ^ (row & 7);
            boff[k][jj] = row * 256 + ch * 16;
        }

    float best[4], best2[4]; int bk[4];
#pragma unroll
    for (int s = 0; s < 4; ++s) { best[s] = 3.4e38f; best2[s] = 3.4e38f; bk[s] = 0; }

    const int wnidx = (wnh * 32 + 2 * (lane & 3)) * 4;

    {
#pragma unroll
        for (int j = 0; j < 4; ++j) {
            int idx = j * 256 + tid;
            int row = idx >> 4, c = idx & 15;
            cpa16(sb + SM_WBUF(0) + row * 256 + ((c ^ (row & 7)) * 16),
                  g_wth + (size_t)row * NUM_E + c * 8);
        }
        if (tid < 32) cpa16(sb + SM_WN(0) + tid * 16, g_wn + tid * 4);
        asm volatile("cp.async.commit_group;" ::: "memory");
    }

    for (int t = 0; t < NTILES; ++t) {
        if (t + 1 < NTILES) {
            int kt = (t + 1) * BN, b = (t + 1) & 1;
#pragma unroll
            for (int j = 0; j < 4; ++j) {
                int idx = j * 256 + tid;
                int row = idx >> 4, c = idx & 15;
                cpa16(sb + SM_WBUF(b) + row * 256 + ((c ^ (row & 7)) * 16),
                      g_wth + (size_t)row * NUM_E + kt + c * 8);
            }
            if (tid < 32) cpa16(sb + SM_WN(b) + tid * 16, g_wn + kt + tid * 4);
            asm volatile("cp.async.commit_group;" ::: "memory");
            asm volatile("cp.async.wait_group 1;" ::: "memory");
        } else {
            asm volatile("cp.async.wait_group 0;" ::: "memory");
        }
        __syncthreads();

        const unsigned whib = sb + SM_WBUF(t & 1);
        float acc[2][4][4];
#pragma unroll
        for (int i = 0; i < 2; ++i)
#pragma unroll
            for (int j = 0; j < 4; ++j)
#pragma unroll
                for (int e = 0; e < 4; ++e) acc[i][j][e] = 0.0f;

#pragma unroll
        for (int k = 0; k < 4; ++k) {
            unsigned bh[2][4];
#pragma unroll
            for (int jj = 0; jj < 2; ++jj) ldsm4t(bh[jj], whib + boff[k][jj]);
#pragma unroll
            for (int i = 0; i < 2; ++i)
#pragma unroll
                for (int j = 0; j < 4; ++j)
                    mma16816(acc[i][j], afh[i][k], bh[j >> 1][(j & 1) * 2],
                             bh[j >> 1][(j & 1) * 2 + 1]);
        }

        const int ktb = t * BN + wnh * 32 + 2 * (lane & 3);
        const char* wnst = smem + SM_WN(t & 1);
#pragma unroll
        for (int j = 0; j < 4; ++j) {
            float2 wn2 = *reinterpret_cast<const float2*>(wnst + wnidx + j * 32);
            int cb = ktb + j * 8;
#pragma unroll
            for (int i = 0; i < 2; ++i) {
#pragma unroll
                for (int hlf = 0; hlf < 2; ++hlf) {
                    int sl = i * 2 + hlf;
                    float s0 = fmaf(-2.0f, acc[i][j][hlf * 2 + 0], wn2.x);
                    float s1 = fmaf(-2.0f, acc[i][j][hlf * 2 + 1], wn2.y);
                    bool lt0 = s0 < best[sl];
                    float old0 = best[sl];
                    best[sl]  = lt0 ? s0 : old0;
                    best2[sl] = fminf(best2[sl], lt0 ? old0 : s0);
                    bk[sl]    = lt0 ? cb : bk[sl];
                    bool lt1 = s1 < best[sl];
                    float old1 = best[sl];
                    best[sl]  = lt1 ? s1 : old1;
                    best2[sl] = fminf(best2[sl], lt1 ? old1 : s1);
                    bk[sl]    = lt1 ? (cb + 1) : bk[sl];
                }
            }
        }
        __syncthreads();
    }

    // quad reduction
#pragma unroll
    for (int off = 1; off <= 2; off <<= 1) {
#pragma unroll
        for (int s = 0; s < 4; ++s) {
            float ob  = __shfl_xor_sync(0xffffffffu, best[s], off);
            float ob2 = __shfl_xor_sync(0xffffffffu, best2[s], off);
            int   ok  = __shfl_xor_sync(0xffffffffu, bk[s], off);
            float nb2 = fminf(fminf(best2[s], ob2), fmaxf(best[s], ob));
            bool take = (ob < best[s]) || (ob == best[s] && ok < bk[s]);
            best[s] = take ? ob : best[s];
            bk[s]   = take ? ok : bk[s];
            best2[s] = nb2;
        }
    }

    // stage per (row, n-group), merge 4 groups
    float* mB  = reinterpret_cast<float*>(smem);
    float* mB2 = mB + 256;
    int*   mK  = reinterpret_cast<int*>(mB2 + 256);
    int*   idx_s = mK + 256;
    float* red   = reinterpret_cast<float*>(idx_s + 64);
    __syncthreads();
    if ((lane & 3) == 0) {
#pragma unroll
        for (int s = 0; s < 4; ++s) {
            int row = wm * 32 + (s >> 1) * 16 + (lane >> 2) + (s & 1) * 8;
            mB [wnh * 64 + row] = best[s];
            mB2[wnh * 64 + row] = best2[s];
            mK [wnh * 64 + row] = bk[s];
        }
    }
    __syncthreads();
    if (tid < 64) {
        float nb = 3.4e38f; int nk = 0, ng = 0;
#pragma unroll
        for (int g = 0; g < 4; ++g) {
            float b = mB[g * 64 + tid];
            int   k = mK[g * 64 + tid];
            if (b < nb || (b == nb && k < nk)) { nb = b; nk = k; ng = g; }
        }
        float nb2 = 3.4e38f;
#pragma unroll
        for (int g = 0; g < 4; ++g) {
            float cand = (g == ng) ? mB2[g * 64 + tid]
                                   : fminf(mB[g * 64 + tid], mB2[g * 64 + tid]);
            nb2 = fminf(nb2, cand);
        }
        g_bestk[n0 + tid] = nk;
        idx_s[tid] = nk;
        out[OFF_IDX + n0 + tid] = (float)nk;
        atomicAdd(&g_counts[nk], 1.0f);
        bool amb = (nb2 - nb) < MARGIN1;
        unsigned m = __ballot_sync(0xffffffffu, amb);
        int basep = 0;
        if (lane == 0 && m) basep = atomicAdd(&g_namb, __popc(m));
        basep = __shfl_sync(0xffffffffu, basep, 0);
        if (amb) g_amb[basep + __popc(m & ((1u << lane) - 1u))] = n0 + tid;
    }
    __syncthreads();

    // fused scatter
    float* outq = out + OFF_Q + (size_t)bB * (CDIM * 4096) + hw0;
    float lsum = 0.0f;
#pragma unroll
    for (int it = 0; it < 4; ++it) {
        int u  = it * 256 + tid;
        int c  = u >> 4;
        int r4 = (u & 15) * 4;
        float4 x4 = *reinterpret_cast<const float4*>(xb + (size_t)c * 4096 + r4);
        int k0i = idx_s[r4 + 0], k1i = idx_s[r4 + 1];
        int k2i = idx_s[r4 + 2], k3i = idx_s[r4 + 3];
        float q0 = __ldg(weight + (size_t)k0i * CDIM + c);
        float q1 = __ldg(weight + (size_t)k1i * CDIM + c);
        float q2 = __ldg(weight + (size_t)k2i * CDIM + c);
        float q3 = __ldg(weight + (size_t)k3i * CDIM + c);
        *reinterpret_cast<float4*>(outq + (size_t)c * 4096 + r4) =
            make_float4(q0, q1, q2, q3);
        float d0 = x4.x - q0, d1 = x4.y - q1, d2 = x4.z - q2, d3 = x4.w - q3;
        lsum += d0 * d0 + d1 * d1 + d2 * d2 + d3 * d3;
        atomicAdd(&g_dw[k0i * CDIM + c], x4.x);
        atomicAdd(&g_dw[k1i * CDIM + c], x4.y);
        atomicAdd(&g_dw[k2i * CDIM + c], x4.z);
        atomicAdd(&g_dw[k3i * CDIM + c], x4.w);
    }
#pragma unroll
    for (int o = 16; o > 0; o >>= 1)
        lsum += __shfl_xor_sync(0xffffffffu, lsum, o);
    if (lane == 0) red[wid] = lsum;
    __syncthreads();
    if (tid == 0) {
        float s = 0.0f;
#pragma unroll
        for (int w = 0; w < 8; ++w) s += red[w];
        atomicAdd(&g_loss, s);
    }
}

// ---------------------------------------------------------------------------
// stage 2: 3-pass split-fp16 re-scan of ambiguous rows + in-place corrections
// ---------------------------------------------------------------------------
__global__ void __launch_bounds__(256, 1)
amb_kernel(const float* __restrict__ inputs,
           const float* __restrict__ weight,
           float* __restrict__ out)
{
    extern __shared__ char smem[];
    const unsigned sb = smem_u32(smem);
    const int tid  = threadIdx.x;
    const int lane = tid & 31;
    const int wid  = tid >> 5;
    const int wm   = wid >> 2;
    const int wnh  = wid & 3;

    const int namb = g_namb;
    if (namb == 0) return;

    int* avid = reinterpret_cast<int*>(smem + A_VID);
    int* cOld = reinterpret_cast<int*>(smem + A_COLD);
    int* cNew = reinterpret_cast<int*>(smem + A_CNEW);

    unsigned boff[4][2];
#pragma unroll
    for (int k = 0; k < 4; ++k)
#pragma unroll
        for (int jj = 0; jj < 2; ++jj) {
            int row = k * 16 + (lane & 15);
            int ch  = (wnh * 4 + jj * 2 + (lane >> 4)) ^ (row & 7);
            boff[k][jj] = row * 256 + ch * 16;
        }
    const int wnidx = (wnh * 32 + 2 * (lane & 3)) * 4;

    for (int base = blockIdx.x * 32; base < namb; base += gridDim.x * 32) {
        __syncthreads();

        if (tid < 32) {
            int li = base + tid;
            avid[tid] = g_amb[li < namb ? li : (namb - 1)];
        }
        __syncthreads();

        {
            int r = tid >> 3;
            int c0 = (tid & 7) * 8;
            int vid = avid[r];
            const float* xr = inputs + (size_t)(vid >> 12) * (CDIM * 4096) + (vid & 4095);
#pragma unroll
            for (int q = 0; q < 8; ++q) {
                int c = c0 + q;
                float v = xr[(size_t)c * 4096];
                __half hi = __float2half_rn(v);
                __half lo = __float2half_rn(v - __half2float(hi));
                unsigned off = r * 128 + (((c >> 3) ^ (r & 7)) * 16) + (c & 7) * 2;
                *reinterpret_cast<__half*>(smem + A_XH + off) = hi;
                *reinterpret_cast<__half*>(smem + A_XL + off) = lo;
            }
        }
        __syncthreads();

        unsigned afh[4][4], afl[4][4];
#pragma unroll
        for (int k = 0; k < 4; ++k) {
            int row = wm * 16 + (lane & 15);
            int ch  = (k * 2 + (lane >> 4)) ^ (row & 7);
            ldsm4(afh[k], sb + A_XH + row * 128 + ch * 16);
            ldsm4(afl[k], sb + A_XL + row * 128 + ch * 16);
        }

        float best[2], best2[2]; int bk[2];
#pragma unroll
        for (int s = 0; s < 2; ++s) { best[s] = 3.4e38f; best2[s] = 3.4e38f; bk[s] = 0; }

        {
#pragma unroll
            for (int j = 0; j < 4; ++j) {
                int idx = j * 256 + tid;
                int row = idx >> 4, c = idx & 15;
                unsigned dsw = row * 256 + ((c ^ (row & 7)) * 16);
                cpa16(sb + A_WB(0)  + dsw, g_wth + (size_t)row * NUM_E + c * 8);
                cpa16(sb + A_WLO(0) + dsw, g_wtl + (size_t)row * NUM_E + c * 8);
            }
            if (tid < 32) cpa16(sb + A_WN(0) + tid * 16, g_wn + tid * 4);
            asm volatile("cp.async.commit_group;" ::: "memory");
        }

        for (int t = 0; t < NTILES; ++t) {
            if (t + 1 < NTILES) {
                int kt = (t + 1) * BN, b = (t + 1) & 1;
#pragma unroll
                for (int j = 0; j < 4; ++j) {
                    int idx = j * 256 + tid;
                    int row = idx >> 4, c = idx & 15;
                    unsigned dsw = row * 256 + ((c ^ (row & 7)) * 16);
                    cpa16(sb + A_WB(b)  + dsw, g_wth + (size_t)row * NUM_E + kt + c * 8);
                    cpa16(sb + A_WLO(b) + dsw, g_wtl + (size_t)row * NUM_E + kt + c * 8);
                }
                if (tid < 32) cpa16(sb + A_WN(b) + tid * 16, g_wn + kt + tid * 4);
                asm volatile("cp.async.commit_group;" ::: "memory");
                asm volatile("cp.async.wait_group 1;" ::: "memory");
            } else {
                asm volatile("cp.async.wait_group 0;" ::: "memory");
            }
            __syncthreads();

            const unsigned whib = sb + A_WB(t & 1);
            const unsigned wlob = sb + A_WLO(t & 1);
            float acc[4][4];
#pragma unroll
            for (int j = 0; j < 4; ++j)
#pragma unroll
                for (int e = 0; e < 4; ++e) acc[j][e] = 0.0f;

#pragma unroll
            for (int k = 0; k < 4; ++k) {
                unsigned bh[2][4], bl[2][4];
#pragma unroll
                for (int jj = 0; jj < 2; ++jj) {
                    ldsm4t(bh[jj], whib + boff[k][jj]);
                    ldsm4t(bl[jj], wlob + boff[k][jj]);
                }
#pragma unroll
                for (int j = 0; j < 4; ++j) {
                    unsigned h0 = bh[j >> 1][(j & 1) * 2], h1 = bh[j >> 1][(j & 1) * 2 + 1];
                    unsigned l0 = bl[j >> 1][(j & 1) * 2], l1 = bl[j >> 1][(j & 1) * 2 + 1];
                    mma16816(acc[j], afh[k], h0, h1);
                    mma16816(acc[j], afl[k], h0, h1);
                    mma16816(acc[j], afh[k], l0, l1);
                }
            }

            const int ktb = t * BN + wnh * 32 + 2 * (lane & 3);
            const char* wnst = smem + A_WN(t & 1);
#pragma unroll
            for (int j = 0; j < 4; ++j) {
                float2 wn2 = *reinterpret_cast<const float2*>(wnst + wnidx + j * 32);
                int cb = ktb + j * 8;
#pragma unroll
                for (int sl = 0; sl < 2; ++sl) {
                    float s0 = fmaf(-2.0f, acc[j][sl * 2 + 0], wn2.x);
                    float s1 = fmaf(-2.0f, acc[j][sl * 2 + 1], wn2.y);
                    bool lt0 = s0 < best[sl];
                    float old0 = best[sl];
                    best[sl]  = lt0 ? s0 : old0;
                    best2[sl] = fminf(best2[sl], lt0 ? old0 : s0);
                    bk[sl]    = lt0 ? cb : bk[sl];
                    bool lt1 = s1 < best[sl];
                    float old1 = best[sl];
                    best[sl]  = lt1 ? s1 : old1;
                    best2[sl] = fminf(best2[sl], lt1 ? old1 : s1);
                    bk[sl]    = lt1 ? (cb + 1) : bk[sl];
                }
            }
            __syncthreads();
        }

#pragma unroll
        for (int off = 1; off <= 2; off <<= 1) {
#pragma unroll
            for (int s = 0; s < 2; ++s) {
                float ob  = __shfl_xor_sync(0xffffffffu, best[s], off);
                float ob2 = __shfl_xor_sync(0xffffffffu, best2[s], off);
                int   ok  = __shfl_xor_sync(0xffffffffu, bk[s], off);
                float nb2 = fminf(fminf(best2[s], ob2), fmaxf(best[s], ob));
                bool take = (ob < best[s]) || (ob == best[s] && ok < bk[s]);
                best[s] = take ? ob : best[s];
                bk[s]   = take ? ok : bk[s];
                best2[s] = nb2;
            }
        }

        float* mB  = reinterpret_cast<float*>(smem);
        float* mB2 = mB + 128;
        int*   mK  = reinterpret_cast<int*>(mB2 + 128);
        __syncthreads();
        if ((lane & 3) == 0) {
#pragma unroll
            for (int s = 0; s < 2; ++s) {
                int row = wm * 16 + (lane >> 2) + s * 8;
                mB [wnh * 32 + row] = best[s];
                mB2[wnh * 32 + row] = best2[s];
                mK [wnh * 32 + row] = bk[s];
            }
        }
        __syncthreads();
        if (tid < 32) {
            float nb = 3.4e38f; int nk = 0, ng = 0;
#pragma unroll
            for (int g = 0; g < 4; ++g) {
                float b = mB[g * 32 + tid];
                int   k = mK[g * 32 + tid];
                if (b < nb || (b == nb && k < nk)) { nb = b; nk = k; ng = g; }
            }
            float nb2 = 3.4e38f;
#pragma unroll
            for (int g = 0; g < 4; ++g) {
                float cand = (g == ng) ? mB2[g * 32 + tid]
                                       : fminf(mB[g * 32 + tid], mB2[g * 32 + tid]);
                nb2 = fminf(nb2, cand);
            }
            int li  = base + tid;
            int vid = avid[tid];
            bool valid = (li < namb);
            int k1 = g_bestk[vid];
            if (valid) g_bestk[vid] = nk;
            cOld[tid] = (valid && nk != k1) ? k1 : -1;
            cNew[tid] = nk;
            bool amb = valid && ((nb2 - nb) < MARGIN2);
            unsigned m = __ballot_sync(0xffffffffu, amb);
            int basep = 0;
            if (lane == 0 && m) basep = atomicAdd(&g_namb2, __popc(m));
            basep = __shfl_sync(0xffffffffu, basep, 0);
            if (amb) {
                int slot = basep + __popc(m & ((1u << lane) - 1u));
                g_amb2[slot] = vid;
                g_fixbest[slot] = 0xFFFFFFFFFFFFFFFFULL;
                g_fixcnt[slot] = 0;
            }
        }
        __syncthreads();

#pragma unroll
        for (int j = 0; j < 4; ++j) {
            int r = wid * 4 + j;
            int kold = cOld[r];
            if (kold >= 0) {
                int vid  = avid[r];
                int knew = cNew[r];
                const float* xr = inputs + (size_t)(vid >> 12) * (CDIM * 4096) + (vid & 4095);
                float* qr = out + OFF_Q + (size_t)(vid >> 12) * (CDIM * 4096) + (vid & 4095);
                float ldelta = 0.0f;
#pragma unroll
                for (int h = 0; h < 2; ++h) {
                    int c = lane + h * 32;
                    float x  = xr[(size_t)c * 4096];
                    float wo = weight[(size_t)kold * CDIM + c];
                    float wn_ = weight[(size_t)knew * CDIM + c];
                    qr[(size_t)c * 4096] = wn_;
                    float dn = x - wn_, doo = x - wo;
                    ldelta += dn * dn - doo * doo;
                    atomicAdd(&g_dw[kold * CDIM + c], -x);
                    atomicAdd(&g_dw[knew * CDIM + c],  x);
                }
#pragma unroll
                for (int o = 16; o > 0; o >>= 1)
                    ldelta += __shfl_xor_sync(0xffffffffu, ldelta, o);
                if (lane == 0) {
                    atomicAdd(&g_loss, ldelta);
                    atomicAdd(&g_counts[kold], -1.0f);
                    atomicAdd(&g_counts[knew],  1.0f);
                    out[OFF_IDX + vid] = (float)knew;
                }
            }
        }
    }
}

// ---------------------------------------------------------------------------
// stage 3 (fused): parallel exact fp32 scan; last-finishing part applies the
// correction in-block using the already-staged xs row.
// ---------------------------------------------------------------------------
__global__ void fixup_kernel(const float* __restrict__ inputs,
                             const float* __restrict__ weight,
                             float* __restrict__ out)
{
    __shared__ float xs[CDIM];
    __shared__ unsigned long long rmin[8];
    __shared__ int sApply, sKold, sKnew;
    const int tid = threadIdx.x;   // 256
    const int namb2 = g_namb2;
    const int items = namb2 * FPARTS;

    for (int it = blockIdx.x; it < items; it += gridDim.x) {
        int li   = it >> 4;          // FPARTS == 16
        int part = it & 15;
        int v  = g_amb2[li];
        int bB = v >> 12, hw = v & 4095;
        __syncthreads();             // xs/rmin reuse guard
        if (tid < CDIM)
            xs[tid] = inputs[(size_t)bB * (CDIM * 4096) + (size_t)tid * 4096 + hw];
        __syncthreads();

        // this part covers 256 codes, one per thread (ascending k; strict <)
        int k = part * 256 + tid;
        const float4* wr = reinterpret_cast<const float4*>(weight + (size_t)k * CDIM);
        float dot = 0.0f;
#pragma unroll
        for (int j = 0; j < 16; ++j) {
            float4 w4 = wr[j];
            dot = fmaf(xs[4 * j + 0], w4.x, dot);
            dot = fmaf(xs[4 * j + 1], w4.y, dot);
            dot = fmaf(xs[4 * j + 2], w4.z, dot);
            dot = fmaf(xs[4 * j + 3], w4.w, dot);
        }
        float s = fmaf(-2.0f, dot, g_wn[k]);
        unsigned long long p =
            ((unsigned long long)encf(s) << 32) | (unsigned)k;
#pragma unroll
        for (int o = 16; o > 0; o >>= 1) {
            unsigned long long q2 = __shfl_xor_sync(0xffffffffu, p, o);
            p = (q2 < p) ? q2 : p;
        }
        if ((tid & 31) == 0) rmin[tid >> 5] = p;
        __syncthreads();
        if (tid == 0) {
            unsigned long long m = rmin[0];
#pragma unroll
            for (int w = 1; w < 8; ++w) m = (rmin[w] < m) ? rmin[w] : m;
            atomicMin(&g_fixbest[li], m);
            __threadfence();
            int done = atomicAdd(&g_fixcnt[li], 1);
            sApply = 0;
            if (done == FPARTS - 1) {
                __threadfence();   // pair with writers' fences: fixbest final
                unsigned long long fin = g_fixbest[li];
                int knew = (int)(unsigned)(fin & 0xFFFFFFFFULL);
                int kold = g_bestk[v];
                if (knew != kold) { sApply = 1; sKold = kold; sKnew = knew; }
            }
        }
        __syncthreads();

        if (sApply && tid < CDIM) {
            int kold = sKold, knew = sKnew;
            float x  = xs[tid];
            float wo = weight[(size_t)kold * CDIM + tid];
            float wn_ = weight[(size_t)knew * CDIM + tid];
            out[OFF_Q + (size_t)bB * (CDIM * 4096) + (size_t)tid * 4096 + hw] = wn_;
            float dn = x - wn_, doo = x - wo;
            float ldelta = dn * dn - doo * doo;
            atomicAdd(&g_dw[kold * CDIM + tid], -x);
            atomicAdd(&g_dw[knew * CDIM + tid],  x);
#pragma unroll
            for (int o = 16; o > 0; o >>= 1)
                ldelta += __shfl_xor_sync(0xffffffffu, ldelta, o);
            if ((tid & 31) == 0) atomicAdd(&g_loss, ldelta);
            if (tid == 0) {
                atomicAdd(&g_counts[kold], -1.0f);
                atomicAdd(&g_counts[knew],  1.0f);
                out[OFF_IDX + v] = (float)knew;
            }
        }
    }
}

// ---------------------------------------------------------------------------
__global__ void finalize1_kernel(const float* __restrict__ ema_cs,
                                 float* __restrict__ out) {
    int k = blockIdx.x * blockDim.x + threadIdx.x;
    float ncs = 0.99f * ema_cs[k] + 0.01f * g_counts[k];
    out[OFF_CS + k] = ncs;
    float s = ncs;
#pragma unroll
    for (int o = 16; o > 0; o >>= 1)
        s += __shfl_xor_sync(0xffffffffu, s, o);
    __shared__ float sh[8];
    if ((threadIdx.x & 31) == 0) sh[threadIdx.x >> 5] = s;
    __syncthreads();
    if (threadIdx.x == 0) {
        float t = 0.0f;
#pragma unroll
        for (int w = 0; w < 8; ++w) t += sh[w];
        atomicAdd(&g_n, t);
    }
}

__global__ void finalize2_kernel(const float* __restrict__ ema_w,
                                 float* __restrict__ out) {
    int i = blockIdx.x * blockDim.x + threadIdx.x;
    int k = i >> 6;
    float n   = g_n;
    float ncs = out[OFF_CS + k];
    float cs  = (ncs + 1e-5f) / (n + (float)NUM_E * 1e-5f) * n;
    float ne  = 0.99f * ema_w[i] + 0.01f * g_dw[i];
    out[OFF_EW + i] = ne;
    out[OFF_W + i]  = ne / cs;
    if (i == 0) out[OFF_LOSS] = 0.25f * g_loss / 4194304.0f;
}

// ---------------------------------------------------------------------------
extern "C" void kernel_launch(void* const* d_in, const int* in_sizes, int n_in,
                              void* d_out, int out_size) {
    const float* inputs = (const float*)d_in[0];
    const float* weight = (const float*)d_in[1];
    const float* ema_cs = (const float*)d_in[2];
    const float* ema_w  = (const float*)d_in[3];
    float* out = (float*)d_out;

    cudaFuncSetAttribute(argmin_kernel,
                         cudaFuncAttributeMaxDynamicSharedMemorySize, SMEM_TOTAL);
    cudaFuncSetAttribute(amb_kernel,
                         cudaFuncAttributeMaxDynamicSharedMemorySize, A_SMEM);

    prep_kernel<<<NUM_E / 64, 256>>>(weight);
    argmin_kernel<<<NVEC / BM, THREADS, SMEM_TOTAL>>>(inputs, weight, out);
    amb_kernel<<<512, 256, A_SMEM>>>(inputs, weight, out);
    fixup_kernel<<<2048, 256>>>(inputs, weight, out);
    finalize1_kernel<<<NUM_E / 256, 256>>>(ema_cs, out);
    finalize2_kernel<<<(NUM_E * CDIM) / 256, 256>>>(ema_w, out);
}

// round 16
// speedup vs baseline: 1.0670x; 1.0092x over previous
#include <cuda_runtime.h>
#include <cuda_fp16.h>

// ---------------------------------------------------------------------------
// EMA Vector Quantizer, round 16 (= R15 + merged finalize, n computed in prep):
//   prep: transpose hi/lo + wn + zero + n = 0.99*sum(ema_cs) + 0.01*NVEC
//   stage 1: 1-pass fp16 HMMA argmin + scatter; BM=64, 2 CTAs/SM, m32 x n32
//   stage 2: 3-pass split-fp16 re-scan of ambiguous rows
//   stage 3: parallel exact fp32 scan with in-block apply
//   finalize: single kernel (new_cs, new_ema_w, new_w, loss)
// ---------------------------------------------------------------------------

#define NUM_E   4096
#define CDIM    64
#define NVEC    65536
#define BM      64
#define BN      128
#define NTILES  (NUM_E / BN)   // 32
#define THREADS 256
#define MARGIN1 0.09f
#define MARGIN2 1.0e-3f
#define FPARTS  16

#define OFF_Q    0
#define OFF_LOSS 4194304
#define OFF_IDX  4194305
#define OFF_W    (OFF_IDX + NVEC)
#define OFF_CS   (OFF_W + NUM_E * CDIM)
#define OFF_EW   (OFF_CS + NUM_E)

// stage-1 smem: X 8K + 2 x (W 16K + wn 512B)
#define SM_XH      0
#define SM_WBUF(b) (8192 + (b) * 16896)
#define SM_WN(b)   (SM_WBUF(b) + 16384)
#define SMEM_TOTAL (8192 + 2 * 16896)       // 41984

// stage-2 smem: 2 x (Whi 16K | Wlo 16K | wn .5K)
#define A_XH     0
#define A_XL     4096
#define A_VID    8192
#define A_COLD   8320
#define A_CNEW   8448
#define A_WB(b)  (9216 + (b) * 33280)
#define A_WLO(b) (A_WB(b) + 16384)
#define A_WN(b)  (A_WB(b) + 32768)
#define A_SMEM   (9216 + 2 * 33280)         // 75776

// device scratch
__device__ __half g_wth[CDIM * NUM_E];
__device__ __half g_wtl[CDIM * NUM_E];
__device__ float  g_wn[NUM_E];
__device__ float  g_counts[NUM_E];
__device__ float  g_dw[NUM_E * CDIM];
__device__ int    g_bestk[NVEC];
__device__ int    g_amb[NVEC];
__device__ int    g_namb;
__device__ int    g_amb2[NVEC];
__device__ int    g_namb2;
__device__ unsigned long long g_fixbest[NVEC];
__device__ int    g_fixcnt[NVEC];
__device__ float  g_loss;
__device__ float  g_n;

// ---- PTX helpers -----------------------------------------------------------
__device__ __forceinline__ unsigned smem_u32(const void* p) {
    return (unsigned)__cvta_generic_to_shared(p);
}
__device__ __forceinline__ void ldsm4(unsigned* r, unsigned addr) {
    asm volatile("ldmatrix.sync.aligned.m8n8.x4.shared.b16 {%0,%1,%2,%3}, [%4];"
                 : "=r"(r[0]), "=r"(r[1]), "=r"(r[2]), "=r"(r[3]) : "r"(addr));
}
__device__ __forceinline__ void ldsm4t(unsigned* r, unsigned addr) {
    asm volatile("ldmatrix.sync.aligned.m8n8.x4.trans.shared.b16 {%0,%1,%2,%3}, [%4];"
                 : "=r"(r[0]), "=r"(r[1]), "=r"(r[2]), "=r"(r[3]) : "r"(addr));
}
__device__ __forceinline__ void mma16816(float* c, const unsigned* a,
                                         unsigned b0, unsigned b1) {
    asm volatile("mma.sync.aligned.m16n8k16.row.col.f32.f16.f16.f32 "
                 "{%0,%1,%2,%3}, {%4,%5,%6,%7}, {%8,%9}, {%0,%1,%2,%3};"
                 : "+f"(c[0]), "+f"(c[1]), "+f"(c[2]), "+f"(c[3])
                 : "r"(a[0]), "r"(a[1]), "r"(a[2]), "r"(a[3]), "r"(b0), "r"(b1));
}
__device__ __forceinline__ void cpa16(unsigned dst, const void* src) {
    asm volatile("cp.async.cg.shared.global [%0], [%1], 16;"
                 :: "r"(dst), "l"(src) : "memory");
}
__device__ __forceinline__ unsigned encf(float f) {
    unsigned u = __float_as_uint(f);
    return (u & 0x80000000u) ? ~u : (u | 0x80000000u);
}

// ---------------------------------------------------------------------------
// prep (merged): tiled transpose hi/lo, wn, zero scratch, n  (grid 64, b 256)
// ---------------------------------------------------------------------------
__global__ void prep_kernel(const float* __restrict__ weight,
                            const float* __restrict__ ema_cs) {
    __shared__ float tile[64][65];
    __shared__ float nred[8];
    const int tid = threadIdx.x;
    const int code0 = blockIdx.x * 64;

#pragma unroll
    for (int it = 0; it < 4; ++it) {
        int flat = it * 256 + tid;
        int code = flat >> 4, j = flat & 15;
        float4 v = reinterpret_cast<const float4*>(weight)[(size_t)(code0 + code) * 16 + j];
        tile[code][j * 4 + 0] = v.x;
        tile[code][j * 4 + 1] = v.y;
        tile[code][j * 4 + 2] = v.z;
        tile[code][j * 4 + 3] = v.w;
    }
    __syncthreads();

    if (tid < 64) {
        float s = 0.0f;
#pragma unroll
        for (int j = 0; j < 64; ++j) { float w = tile[tid][j]; s = fmaf(w, w, s); }
        g_wn[code0 + tid] = s;
        g_counts[code0 + tid] = 0.0f;
    }

#pragma unroll
    for (int it = 0; it < 16; ++it) {
        int flat = it * 256 + tid;
        int c = flat >> 6, code = flat & 63;
        float w = tile[code][c];
        __half hi = __float2half_rn(w);
        __half lo = __float2half_rn(w - __half2float(hi));
        g_wth[(size_t)c * NUM_E + code0 + code] = hi;
        g_wtl[(size_t)c * NUM_E + code0 + code] = lo;
    }

    float4 z = make_float4(0.f, 0.f, 0.f, 0.f);
#pragma unroll
    for (int it = 0; it < 4; ++it)
        reinterpret_cast<float4*>(g_dw)[blockIdx.x * 1024 + it * 256 + tid] = z;

    // block 0: n = 0.99 * sum(ema_cs) + 0.01 * NVEC  (sum(counts) == NVEC exactly)
    if (blockIdx.x == 0) {
        float s = 0.0f;
#pragma unroll
        for (int j = 0; j < 16; ++j) s += ema_cs[j * 256 + tid];
#pragma unroll
        for (int o = 16; o > 0; o >>= 1)
            s += __shfl_xor_sync(0xffffffffu, s, o);
        if ((tid & 31) == 0) nred[tid >> 5] = s;
        __syncthreads();
        if (tid == 0) {
            float S = 0.0f;
#pragma unroll
            for (int w = 0; w < 8; ++w) S += nred[w];
            g_n = 0.99f * S + 0.01f * (float)NVEC;
            g_loss = 0.0f; g_namb = 0; g_namb2 = 0;
        }
    }
}

// ---------------------------------------------------------------------------
// stage 1 (fused): argmin + scatter; BM=64, 2 CTAs/SM, warp tile m32 x n32
// ---------------------------------------------------------------------------
__global__ void __launch_bounds__(THREADS, 2)
argmin_kernel(const float* __restrict__ inputs,
              const float* __restrict__ weight,
              float* __restrict__ out)
{
    extern __shared__ char smem[];
    const unsigned sb = smem_u32(smem);
    const int tid  = threadIdx.x;
    const int lane = tid & 31;
    const int wid  = tid >> 5;
    const int wm   = wid >> 2;     // 0..1 (m32 slice)
    const int wnh  = wid & 3;      // 0..3 (n32 group)

    const int n0  = blockIdx.x * BM;
    const int bB  = n0 >> 12;
    const int hw0 = n0 & 4095;

    const float* xb = inputs + (size_t)bB * (CDIM * 4096) + hw0;
#pragma unroll
    for (int it = 0; it < 2; ++it) {
        int idx = it * 256 + tid;
        int c = (idx & 31) * 2;
        int r = (idx >> 5) * 4;
        float4 f0 = *reinterpret_cast<const float4*>(xb + (size_t)c * 4096 + r);
        float4 f1 = *reinterpret_cast<const float4*>(xb + (size_t)(c + 1) * 4096 + r);
        const float* p0 = &f0.x; const float* p1 = &f1.x;
#pragma unroll
        for (int q = 0; q < 4; ++q) {
            int row = r + q;
            unsigned off = row * 128 + (((c >> 3) ^ (row & 7)) * 16) + (c & 7) * 2;
            *reinterpret_cast<__half2*>(smem + SM_XH + off) =
                __floats2half2_rn(p0[q], p1[q]);
        }
    }
    __syncthreads();

    unsigned afh[2][4][4];
#pragma unroll
    for (int i = 0; i < 2; ++i)
#pragma unroll
        for (int k = 0; k < 4; ++k) {
            int row = wm * 32 + i * 16 + (lane & 15);
            int ch  = (k * 2 + (lane >> 4)) ^ (row & 7);
            ldsm4(afh[i][k], sb + SM_XH + row * 128 + ch * 16);
        }

    unsigned boff[4][2];
#pragma unroll
    for (int k = 0; k < 4; ++k)
#pragma unroll
        for (int jj = 0; jj < 2; ++jj) {
            int row = k * 16 + (lane & 15);
            int ch  = (wnh * 4 + jj * 2 + (lane >> 4)) ^ (row & 7);
            boff[k][jj] = row * 256 + ch * 16;
        }

    float best[4], best2[4]; int bk[4];
#pragma unroll
    for (int s = 0; s < 4; ++s) { best[s] = 3.4e38f; best2[s] = 3.4e38f; bk[s] = 0; }

    const int wnidx = (wnh * 32 + 2 * (lane & 3)) * 4;

    {
#pragma unroll
        for (int j = 0; j < 4; ++j) {
            int idx = j * 256 + tid;
            int row = idx >> 4, c = idx & 15;
            cpa16(sb + SM_WBUF(0) + row * 256 + ((c ^ (row & 7)) * 16),
                  g_wth + (size_t)row * NUM_E + c * 8);
        }
        if (tid < 32) cpa16(sb + SM_WN(0) + tid * 16, g_wn + tid * 4);
        asm volatile("cp.async.commit_group;" ::: "memory");
    }

    for (int t = 0; t < NTILES; ++t) {
        if (t + 1 < NTILES) {
            int kt = (t + 1) * BN, b = (t + 1) & 1;
#pragma unroll
            for (int j = 0; j < 4; ++j) {
                int idx = j * 256 + tid;
                int row = idx >> 4, c = idx & 15;
                cpa16(sb + SM_WBUF(b) + row * 256 + ((c ^ (row & 7)) * 16),
                      g_wth + (size_t)row * NUM_E + kt + c * 8);
            }
            if (tid < 32) cpa16(sb + SM_WN(b) + tid * 16, g_wn + kt + tid * 4);
            asm volatile("cp.async.commit_group;" ::: "memory");
            asm volatile("cp.async.wait_group 1;" ::: "memory");
        } else {
            asm volatile("cp.async.wait_group 0;" ::: "memory");
        }
        __syncthreads();

        const unsigned whib = sb + SM_WBUF(t & 1);
        float acc[2][4][4];
#pragma unroll
        for (int i = 0; i < 2; ++i)
#pragma unroll
            for (int j = 0; j < 4; ++j)
#pragma unroll
                for (int e = 0; e < 4; ++e) acc[i][j][e] = 0.0f;

#pragma unroll
        for (int k = 0; k < 4; ++k) {
            unsigned bh[2][4];
#pragma unroll
            for (int jj = 0; jj < 2; ++jj) ldsm4t(bh[jj], whib + boff[k][jj]);
#pragma unroll
            for (int i = 0; i < 2; ++i)
#pragma unroll
                for (int j = 0; j < 4; ++j)
                    mma16816(acc[i][j], afh[i][k], bh[j >> 1][(j & 1) * 2],
                             bh[j >> 1][(j & 1) * 2 + 1]);
        }

        const int ktb = t * BN + wnh * 32 + 2 * (lane & 3);
        const char* wnst = smem + SM_WN(t & 1);
#pragma unroll
        for (int j = 0; j < 4; ++j) {
            float2 wn2 = *reinterpret_cast<const float2*>(wnst + wnidx + j * 32);
            int cb = ktb + j * 8;
#pragma unroll
            for (int i = 0; i < 2; ++i) {
#pragma unroll
                for (int hlf = 0; hlf < 2; ++hlf) {
                    int sl = i * 2 + hlf;
                    float s0 = fmaf(-2.0f, acc[i][j][hlf * 2 + 0], wn2.x);
                    float s1 = fmaf(-2.0f, acc[i][j][hlf * 2 + 1], wn2.y);
                    bool lt0 = s0 < best[sl];
                    float old0 = best[sl];
                    best[sl]  = lt0 ? s0 : old0;
                    best2[sl] = fminf(best2[sl], lt0 ? old0 : s0);
                    bk[sl]    = lt0 ? cb : bk[sl];
                    bool lt1 = s1 < best[sl];
                    float old1 = best[sl];
                    best[sl]  = lt1 ? s1 : old1;
                    best2[sl] = fminf(best2[sl], lt1 ? old1 : s1);
                    bk[sl]    = lt1 ? (cb + 1) : bk[sl];
                }
            }
        }
        __syncthreads();
    }

    // quad reduction
#pragma unroll
    for (int off = 1; off <= 2; off <<= 1) {
#pragma unroll
        for (int s = 0; s < 4; ++s) {
            float ob  = __shfl_xor_sync(0xffffffffu, best[s], off);
            float ob2 = __shfl_xor_sync(0xffffffffu, best2[s], off);
            int   ok  = __shfl_xor_sync(0xffffffffu, bk[s], off);
            float nb2 = fminf(fminf(best2[s], ob2), fmaxf(best[s], ob));
            bool take = (ob < best[s]) || (ob == best[s] && ok < bk[s]);
            best[s] = take ? ob : best[s];
            bk[s]   = take ? ok : bk[s];
            best2[s] = nb2;
        }
    }

    float* mB  = reinterpret_cast<float*>(smem);
    float* mB2 = mB + 256;
    int*   mK  = reinterpret_cast<int*>(mB2 + 256);
    int*   idx_s = mK + 256;
    float* red   = reinterpret_cast<float*>(idx_s + 64);
    __syncthreads();
    if ((lane & 3) == 0) {
#pragma unroll
        for (int s = 0; s < 4; ++s) {
            int row = wm * 32 + (s >> 1) * 16 + (lane >> 2) + (s & 1) * 8;
            mB [wnh * 64 + row] = best[s];
            mB2[wnh * 64 + row] = best2[s];
            mK [wnh * 64 + row] = bk[s];
        }
    }
    __syncthreads();
    if (tid < 64) {
        float nb = 3.4e38f; int nk = 0, ng = 0;
#pragma unroll
        for (int g = 0; g < 4; ++g) {
            float b = mB[g * 64 + tid];
            int   k = mK[g * 64 + tid];
            if (b < nb || (b == nb && k < nk)) { nb = b; nk = k; ng = g; }
        }
        float nb2 = 3.4e38f;
#pragma unroll
        for (int g = 0; g < 4; ++g) {
            float cand = (g == ng) ? mB2[g * 64 + tid]
                                   : fminf(mB[g * 64 + tid], mB2[g * 64 + tid]);
            nb2 = fminf(nb2, cand);
        }
        g_bestk[n0 + tid] = nk;
        idx_s[tid] = nk;
        out[OFF_IDX + n0 + tid] = (float)nk;
        atomicAdd(&g_counts[nk], 1.0f);
        bool amb = (nb2 - nb) < MARGIN1;
        unsigned m = __ballot_sync(0xffffffffu, amb);
        int basep = 0;
        if (lane == 0 && m) basep = atomicAdd(&g_namb, __popc(m));
        basep = __shfl_sync(0xffffffffu, basep, 0);
        if (amb) g_amb[basep + __popc(m & ((1u << lane) - 1u))] = n0 + tid;
    }
    __syncthreads();

    float* outq = out + OFF_Q + (size_t)bB * (CDIM * 4096) + hw0;
    float lsum = 0.0f;
#pragma unroll
    for (int it = 0; it < 4; ++it) {
        int u  = it * 256 + tid;
        int c  = u >> 4;
        int r4 = (u & 15) * 4;
        float4 x4 = *reinterpret_cast<const float4*>(xb + (size_t)c * 4096 + r4);
        int k0i = idx_s[r4 + 0], k1i = idx_s[r4 + 1];
        int k2i = idx_s[r4 + 2], k3i = idx_s[r4 + 3];
        float q0 = __ldg(weight + (size_t)k0i * CDIM + c);
        float q1 = __ldg(weight + (size_t)k1i * CDIM + c);
        float q2 = __ldg(weight + (size_t)k2i * CDIM + c);
        float q3 = __ldg(weight + (size_t)k3i * CDIM + c);
        *reinterpret_cast<float4*>(outq + (size_t)c * 4096 + r4) =
            make_float4(q0, q1, q2, q3);
        float d0 = x4.x - q0, d1 = x4.y - q1, d2 = x4.z - q2, d3 = x4.w - q3;
        lsum += d0 * d0 + d1 * d1 + d2 * d2 + d3 * d3;
        atomicAdd(&g_dw[k0i * CDIM + c], x4.x);
        atomicAdd(&g_dw[k1i * CDIM + c], x4.y);
        atomicAdd(&g_dw[k2i * CDIM + c], x4.z);
        atomicAdd(&g_dw[k3i * CDIM + c], x4.w);
    }
#pragma unroll
    for (int o = 16; o > 0; o >>= 1)
        lsum += __shfl_xor_sync(0xffffffffu, lsum, o);
    if (lane == 0) red[wid] = lsum;
    __syncthreads();
    if (tid == 0) {
        float s = 0.0f;
#pragma unroll
        for (int w = 0; w < 8; ++w) s += red[w];
        atomicAdd(&g_loss, s);
    }
}

// ---------------------------------------------------------------------------
// stage 2: 3-pass split-fp16 re-scan of ambiguous rows + in-place corrections
// ---------------------------------------------------------------------------
__global__ void __launch_bounds__(256, 1)
amb_kernel(const float* __restrict__ inputs,
           const float* __restrict__ weight,
           float* __restrict__ out)
{
    extern __shared__ char smem[];
    const unsigned sb = smem_u32(smem);
    const int tid  = threadIdx.x;
    const int lane = tid & 31;
    const int wid  = tid >> 5;
    const int wm   = wid >> 2;
    const int wnh  = wid & 3;

    const int namb = g_namb;
    if (namb == 0) return;

    int* avid = reinterpret_cast<int*>(smem + A_VID);
    int* cOld = reinterpret_cast<int*>(smem + A_COLD);
    int* cNew = reinterpret_cast<int*>(smem + A_CNEW);

    unsigned boff[4][2];
#pragma unroll
    for (int k = 0; k < 4; ++k)
#pragma unroll
        for (int jj = 0; jj < 2; ++jj) {
            int row = k * 16 + (lane & 15);
            int ch  = (wnh * 4 + jj * 2 + (lane >> 4)) ^ (row & 7);
            boff[k][jj] = row * 256 + ch * 16;
        }
    const int wnidx = (wnh * 32 + 2 * (lane & 3)) * 4;

    for (int base = blockIdx.x * 32; base < namb; base += gridDim.x * 32) {
        __syncthreads();

        if (tid < 32) {
            int li = base + tid;
            avid[tid] = g_amb[li < namb ? li : (namb - 1)];
        }
        __syncthreads();

        {
            int r = tid >> 3;
            int c0 = (tid & 7) * 8;
            int vid = avid[r];
            const float* xr = inputs + (size_t)(vid >> 12) * (CDIM * 4096) + (vid & 4095);
#pragma unroll
            for (int q = 0; q < 8; ++q) {
                int c = c0 + q;
                float v = xr[(size_t)c * 4096];
                __half hi = __float2half_rn(v);
                __half lo = __float2half_rn(v - __half2float(hi));
                unsigned off = r * 128 + (((c >> 3) ^ (r & 7)) * 16) + (c & 7) * 2;
                *reinterpret_cast<__half*>(smem + A_XH + off) = hi;
                *reinterpret_cast<__half*>(smem + A_XL + off) = lo;
            }
        }
        __syncthreads();

        unsigned afh[4][4], afl[4][4];
#pragma unroll
        for (int k = 0; k < 4; ++k) {
            int row = wm * 16 + (lane & 15);
            int ch  = (k * 2 + (lane >> 4)) ^ (row & 7);
            ldsm4(afh[k], sb + A_XH + row * 128 + ch * 16);
            ldsm4(afl[k], sb + A_XL + row * 128 + ch * 16);
        }

        float best[2], best2[2]; int bk[2];
#pragma unroll
        for (int s = 0; s < 2; ++s) { best[s] = 3.4e38f; best2[s] = 3.4e38f; bk[s] = 0; }

        {
#pragma unroll
            for (int j = 0; j < 4; ++j) {
                int idx = j * 256 + tid;
                int row = idx >> 4, c = idx & 15;
                unsigned dsw = row * 256 + ((c ^ (row & 7)) * 16);
                cpa16(sb + A_WB(0)  + dsw, g_wth + (size_t)row * NUM_E + c * 8);
                cpa16(sb + A_WLO(0) + dsw, g_wtl + (size_t)row * NUM_E + c * 8);
            }
            if (tid < 32) cpa16(sb + A_WN(0) + tid * 16, g_wn + tid * 4);
            asm volatile("cp.async.commit_group;" ::: "memory");
        }

        for (int t = 0; t < NTILES; ++t) {
            if (t + 1 < NTILES) {
                int kt = (t + 1) * BN, b = (t + 1) & 1;
#pragma unroll
                for (int j = 0; j < 4; ++j) {
                    int idx = j * 256 + tid;
                    int row = idx >> 4, c = idx & 15;
                    unsigned dsw = row * 256 + ((c ^ (row & 7)) * 16);
                    cpa16(sb + A_WB(b)  + dsw, g_wth + (size_t)row * NUM_E + kt + c * 8);
                    cpa16(sb + A_WLO(b) + dsw, g_wtl + (size_t)row * NUM_E + kt + c * 8);
                }
                if (tid < 32) cpa16(sb + A_WN(b) + tid * 16, g_wn + kt + tid * 4);
                asm volatile("cp.async.commit_group;" ::: "memory");
                asm volatile("cp.async.wait_group 1;" ::: "memory");
            } else {
                asm volatile("cp.async.wait_group 0;" ::: "memory");
            }
            __syncthreads();

            const unsigned whib = sb + A_WB(t & 1);
            const unsigned wlob = sb + A_WLO(t & 1);
            float acc[4][4];
#pragma unroll
            for (int j = 0; j < 4; ++j)
#pragma unroll
                for (int e = 0; e < 4; ++e) acc[j][e] = 0.0f;

#pragma unroll
            for (int k = 0; k < 4; ++k) {
                unsigned bh[2][4], bl[2][4];
#pragma unroll
                for (int jj = 0; jj < 2; ++jj) {
                    ldsm4t(bh[jj], whib + boff[k][jj]);
                    ldsm4t(bl[jj], wlob + boff[k][jj]);
                }
#pragma unroll
                for (int j = 0; j < 4; ++j) {
                    unsigned h0 = bh[j >> 1][(j & 1) * 2], h1 = bh[j >> 1][(j & 1) * 2 + 1];
                    unsigned l0 = bl[j >> 1][(j & 1) * 2], l1 = bl[j >> 1][(j & 1) * 2 + 1];
                    mma16816(acc[j], afh[k], h0, h1);
                    mma16816(acc[j], afl[k], h0, h1);
                    mma16816(acc[j], afh[k], l0, l1);
                }
            }

            const int ktb = t * BN + wnh * 32 + 2 * (lane & 3);
            const char* wnst = smem + A_WN(t & 1);
#pragma unroll
            for (int j = 0; j < 4; ++j) {
                float2 wn2 = *reinterpret_cast<const float2*>(wnst + wnidx + j * 32);
                int cb = ktb + j * 8;
#pragma unroll
                for (int sl = 0; sl < 2; ++sl) {
                    float s0 = fmaf(-2.0f, acc[j][sl * 2 + 0], wn2.x);
                    float s1 = fmaf(-2.0f, acc[j][sl * 2 + 1], wn2.y);
                    bool lt0 = s0 < best[sl];
                    float old0 = best[sl];
                    best[sl]  = lt0 ? s0 : old0;
                    best2[sl] = fminf(best2[sl], lt0 ? old0 : s0);
                    bk[sl]    = lt0 ? cb : bk[sl];
                    bool lt1 = s1 < best[sl];
                    float old1 = best[sl];
                    best[sl]  = lt1 ? s1 : old1;
                    best2[sl] = fminf(best2[sl], lt1 ? old1 : s1);
                    bk[sl]    = lt1 ? (cb + 1) : bk[sl];
                }
            }
            __syncthreads();
        }

#pragma unroll
        for (int off = 1; off <= 2; off <<= 1) {
#pragma unroll
            for (int s = 0; s < 2; ++s) {
                float ob  = __shfl_xor_sync(0xffffffffu, best[s], off);
                float ob2 = __shfl_xor_sync(0xffffffffu, best2[s], off);
                int   ok  = __shfl_xor_sync(0xffffffffu, bk[s], off);
                float nb2 = fminf(fminf(best2[s], ob2), fmaxf(best[s], ob));
                bool take = (ob < best[s]) || (ob == best[s] && ok < bk[s]);
                best[s] = take ? ob : best[s];
                bk[s]   = take ? ok : bk[s];
                best2[s] = nb2;
            }
        }

        float* mB  = reinterpret_cast<float*>(smem);
        float* mB2 = mB + 128;
        int*   mK  = reinterpret_cast<int*>(mB2 + 128);
        __syncthreads();
        if ((lane & 3) == 0) {
#pragma unroll
            for (int s = 0; s < 2; ++s) {
                int row = wm * 16 + (lane >> 2) + s * 8;
                mB [wnh * 32 + row] = best[s];
                mB2[wnh * 32 + row] = best2[s];
                mK [wnh * 32 + row] = bk[s];
            }
        }
        __syncthreads();
        if (tid < 32) {
            float nb = 3.4e38f; int nk = 0, ng = 0;
#pragma unroll
            for (int g = 0; g < 4; ++g) {
                float b = mB[g * 32 + tid];
                int   k = mK[g * 32 + tid];
                if (b < nb || (b == nb && k < nk)) { nb = b; nk = k; ng = g; }
            }
            float nb2 = 3.4e38f;
#pragma unroll
            for (int g = 0; g < 4; ++g) {
                float cand = (g == ng) ? mB2[g * 32 + tid]
                                       : fminf(mB[g * 32 + tid], mB2[g * 32 + tid]);
                nb2 = fminf(nb2, cand);
            }
            int li  = base + tid;
            int vid = avid[tid];
            bool valid = (li < namb);
            int k1 = g_bestk[vid];
            if (valid) g_bestk[vid] = nk;
            cOld[tid] = (valid && nk != k1) ? k1 : -1;
            cNew[tid] = nk;
            bool amb = valid && ((nb2 - nb) < MARGIN2);
            unsigned m = __ballot_sync(0xffffffffu, amb);
            int basep = 0;
            if (lane == 0 && m) basep = atomicAdd(&g_namb2, __popc(m));
            basep = __shfl_sync(0xffffffffu, basep, 0);
            if (amb) {
                int slot = basep + __popc(m & ((1u << lane) - 1u));
                g_amb2[slot] = vid;
                g_fixbest[slot] = 0xFFFFFFFFFFFFFFFFULL;
                g_fixcnt[slot] = 0;
            }
        }
        __syncthreads();

#pragma unroll
        for (int j = 0; j < 4; ++j) {
            int r = wid * 4 + j;
            int kold = cOld[r];
            if (kold >= 0) {
                int vid  = avid[r];
                int knew = cNew[r];
                const float* xr = inputs + (size_t)(vid >> 12) * (CDIM * 4096) + (vid & 4095);
                float* qr = out + OFF_Q + (size_t)(vid >> 12) * (CDIM * 4096) + (vid & 4095);
                float ldelta = 0.0f;
#pragma unroll
                for (int h = 0; h < 2; ++h) {
                    int c = lane + h * 32;
                    float x  = xr[(size_t)c * 4096];
                    float wo = weight[(size_t)kold * CDIM + c];
                    float wn_ = weight[(size_t)knew * CDIM + c];
                    qr[(size_t)c * 4096] = wn_;
                    float dn = x - wn_, doo = x - wo;
                    ldelta += dn * dn - doo * doo;
                    atomicAdd(&g_dw[kold * CDIM + c], -x);
                    atomicAdd(&g_dw[knew * CDIM + c],  x);
                }
#pragma unroll
                for (int o = 16; o > 0; o >>= 1)
                    ldelta += __shfl_xor_sync(0xffffffffu, ldelta, o);
                if (lane == 0) {
                    atomicAdd(&g_loss, ldelta);
                    atomicAdd(&g_counts[kold], -1.0f);
                    atomicAdd(&g_counts[knew],  1.0f);
                    out[OFF_IDX + vid] = (float)knew;
                }
            }
        }
    }
}

// ---------------------------------------------------------------------------
// stage 3 (fused): parallel exact fp32 scan; last part applies in-block
// ---------------------------------------------------------------------------
__global__ void fixup_kernel(const float* __restrict__ inputs,
                             const float* __restrict__ weight,
                             float* __restrict__ out)
{
    __shared__ float xs[CDIM];
    __shared__ unsigned long long rmin[8];
    __shared__ int sApply, sKold, sKnew;
    const int tid = threadIdx.x;   // 256
    const int namb2 = g_namb2;
    const int items = namb2 * FPARTS;

    for (int it = blockIdx.x; it < items; it += gridDim.x) {
        int li   = it >> 4;
        int part = it & 15;
        int v  = g_amb2[li];
        int bB = v >> 12, hw = v & 4095;
        __syncthreads();
        if (tid < CDIM)
            xs[tid] = inputs[(size_t)bB * (CDIM * 4096) + (size_t)tid * 4096 + hw];
        __syncthreads();

        int k = part * 256 + tid;
        const float4* wr = reinterpret_cast<const float4*>(weight + (size_t)k * CDIM);
        float dot = 0.0f;
#pragma unroll
        for (int j = 0; j < 16; ++j) {
            float4 w4 = wr[j];
            dot = fmaf(xs[4 * j + 0], w4.x, dot);
            dot = fmaf(xs[4 * j + 1], w4.y, dot);
            dot = fmaf(xs[4 * j + 2], w4.z, dot);
            dot = fmaf(xs[4 * j + 3], w4.w, dot);
        }
        float s = fmaf(-2.0f, dot, g_wn[k]);
        unsigned long long p =
            ((unsigned long long)encf(s) << 32) | (unsigned)k;
#pragma unroll
        for (int o = 16; o > 0; o >>= 1) {
            unsigned long long q2 = __shfl_xor_sync(0xffffffffu, p, o);
            p = (q2 < p) ? q2 : p;
        }
        if ((tid & 31) == 0) rmin[tid >> 5] = p;
        __syncthreads();
        if (tid == 0) {
            unsigned long long m = rmin[0];
#pragma unroll
            for (int w = 1; w < 8; ++w) m = (rmin[w] < m) ? rmin[w] : m;
            atomicMin(&g_fixbest[li], m);
            __threadfence();
            int done = atomicAdd(&g_fixcnt[li], 1);
            sApply = 0;
            if (done == FPARTS - 1) {
                __threadfence();
                unsigned long long fin = g_fixbest[li];
                int knew = (int)(unsigned)(fin & 0xFFFFFFFFULL);
                int kold = g_bestk[v];
                if (knew != kold) { sApply = 1; sKold = kold; sKnew = knew; }
            }
        }
        __syncthreads();

        if (sApply && tid < CDIM) {
            int kold = sKold, knew = sKnew;
            float x  = xs[tid];
            float wo = weight[(size_t)kold * CDIM + tid];
            float wn_ = weight[(size_t)knew * CDIM + tid];
            out[OFF_Q + (size_t)bB * (CDIM * 4096) + (size_t)tid * 4096 + hw] = wn_;
            float dn = x - wn_, doo = x - wo;
            float ldelta = dn * dn - doo * doo;
            atomicAdd(&g_dw[kold * CDIM + tid], -x);
            atomicAdd(&g_dw[knew * CDIM + tid],  x);
#pragma unroll
            for (int o = 16; o > 0; o >>= 1)
                ldelta += __shfl_xor_sync(0xffffffffu, ldelta, o);
            if ((tid & 31) == 0) atomicAdd(&g_loss, ldelta);
            if (tid == 0) {
                atomicAdd(&g_counts[kold], -1.0f);
                atomicAdd(&g_counts[knew],  1.0f);
                out[OFF_IDX + v] = (float)knew;
            }
        }
    }
}

// ---------------------------------------------------------------------------
// finalize (merged): new_cs, new_ema_w, new_w, loss  (grid 1024, block 256)
// ---------------------------------------------------------------------------
__global__ void finalize_kernel(const float* __restrict__ ema_cs,
                                const float* __restrict__ ema_w,
                                float* __restrict__ out) {
    int i = blockIdx.x * blockDim.x + threadIdx.x;   // 262144
    int k = i >> 6;
    float n   = g_n;
    float ncs = 0.99f * ema_cs[k] + 0.01f * g_counts[k];
    if ((i & 63) == 0) out[OFF_CS + k] = ncs;
    float cs  = (ncs + 1e-5f) / (n + (float)NUM_E * 1e-5f) * n;
    float ne  = 0.99f * ema_w[i] + 0.01f * g_dw[i];
    out[OFF_EW + i] = ne;
    out[OFF_W + i]  = ne / cs;
    if (i == 0) out[OFF_LOSS] = 0.25f * g_loss / 4194304.0f;
}

// ---------------------------------------------------------------------------
extern "C" void kernel_launch(void* const* d_in, const int* in_sizes, int n_in,
                              void* d_out, int out_size) {
    const float* inputs = (const float*)d_in[0];
    const float* weight = (const float*)d_in[1];
    const float* ema_cs = (const float*)d_in[2];
    const float* ema_w  = (const float*)d_in[3];
    float* out = (float*)d_out;

    cudaFuncSetAttribute(argmin_kernel,
                         cudaFuncAttributeMaxDynamicSharedMemorySize, SMEM_TOTAL);
    cudaFuncSetAttribute(amb_kernel,
                         cudaFuncAttributeMaxDynamicSharedMemorySize, A_SMEM);

    prep_kernel<<<NUM_E / 64, 256>>>(weight, ema_cs);
    argmin_kernel<<<NVEC / BM, THREADS, SMEM_TOTAL>>>(inputs, weight, out);
    amb_kernel<<<512, 256, A_SMEM>>>(inputs, weight, out);
    fixup_kernel<<<2048, 256>>>(inputs, weight, out);
    finalize_kernel<<<(NUM_E * CDIM) / 256, 256>>>(ema_cs, ema_w, out);
}